// round 1
// baseline (speedup 1.0000x reference)
#include <cuda_runtime.h>
#include <math.h>

#define BB 64
#define TT 512
#define NK 512
#define DD 256
#define EPSLN 1e-5f

// ---------------- scratch (device globals: alloc-guard-safe) ----------------
__device__ float g_x[BB*TT*DD];
__device__ float g_q[BB*TT*DD];
__device__ float g_k[BB*NK*DD];
__device__ float g_v[BB*NK*DD];
__device__ float g_attn[BB*TT*NK];   // 16.7M floats = 64MB
__device__ float g_enc[BB*TT*DD];

// ---------------- reductions ----------------
__device__ __forceinline__ float warp_sum(float v) {
    #pragma unroll
    for (int o = 16; o > 0; o >>= 1) v += __shfl_xor_sync(0xffffffffu, v, o);
    return v;
}
__device__ __forceinline__ float warp_max(float v) {
    #pragma unroll
    for (int o = 16; o > 0; o >>= 1) v = fmaxf(v, __shfl_xor_sync(0xffffffffu, v, o));
    return v;
}
__device__ __forceinline__ float block_sum(float v, float* red) {
    int lane = threadIdx.x & 31, wid = threadIdx.x >> 5;
    v = warp_sum(v);
    if (lane == 0) red[wid] = v;
    __syncthreads();
    v = (threadIdx.x < (blockDim.x >> 5)) ? red[threadIdx.x] : 0.f;
    if (wid == 0) v = warp_sum(v);
    if (threadIdx.x == 0) red[0] = v;
    __syncthreads();
    v = red[0];
    __syncthreads();
    return v;
}
__device__ __forceinline__ float block_max(float v, float* red) {
    int lane = threadIdx.x & 31, wid = threadIdx.x >> 5;
    v = warp_max(v);
    if (lane == 0) red[wid] = v;
    __syncthreads();
    v = (threadIdx.x < (blockDim.x >> 5)) ? red[threadIdx.x] : -3.4e38f;
    if (wid == 0) v = warp_max(v);
    if (threadIdx.x == 0) red[0] = v;
    __syncthreads();
    v = red[0];
    __syncthreads();
    return v;
}

// ---------------- x = leaky(LN(traj@w_mlp + b)) + emb[labels] ----------------
__global__ __launch_bounds__(256) void build_x_kernel(
    const float* __restrict__ traj, const int* __restrict__ labels,
    const float* __restrict__ w_mlp, const float* __restrict__ b_mlp,
    const float* __restrict__ ln_g, const float* __restrict__ ln_b,
    const float* __restrict__ emb)
{
    int row = blockIdx.x;            // 0 .. B*T-1
    int b   = row >> 9;              // T = 512
    int d   = threadIdx.x;           // 0 .. 255
    float t0 = traj[row*2 + 0];
    float t1 = traj[row*2 + 1];
    float v  = t0 * w_mlp[d] + t1 * w_mlp[DD + d] + b_mlp[d];

    __shared__ float red[32];
    float mean = block_sum(v, red) * (1.f/DD);
    float dv   = v - mean;
    float var  = block_sum(dv*dv, red) * (1.f/DD);
    float y = dv * rsqrtf(var + EPSLN) * ln_g[d] + ln_b[d];
    y = (y > 0.f) ? y : 0.01f * y;   // leaky_relu default slope
    g_x[(long)row*DD + d] = y + emb[labels[b]*DD + d];
}

// ---------------- generic tiled SGEMM ----------------
// C[M,N] = scale * (A[M,K] @ op(B)) (+ bias[n]); op(B)=B[K,N] (NN) or B[N,K]^T (NT)
// BM=BN=64, BK=16, 256 threads, 4x4 micro-tile. Batched via blockIdx.z.
template<bool TRANSB, bool HASBIAS>
__global__ __launch_bounds__(256) void gemm_tile_kernel(
    const float* __restrict__ A, const float* __restrict__ Bm,
    const float* __restrict__ bias, float* __restrict__ C,
    int M, int N, int K, long strA, long strB, long strC, float scale)
{
    A  += (long)blockIdx.z * strA;
    Bm += (long)blockIdx.z * strB;
    C  += (long)blockIdx.z * strC;
    const int m0 = blockIdx.y * 64;
    const int n0 = blockIdx.x * 64;

    __shared__ float sA[16][64];
    __shared__ float sB[16][64];

    const int tid  = threadIdx.x;
    const int tx   = tid & 15;       // n group
    const int ty   = tid >> 4;       // m group
    const int lrow = tid >> 2;       // 0..63 (A / NT-B loader row)
    const int lkq  = (tid & 3) * 4;  // 0,4,8,12
    const int brow = tid >> 4;       // 0..15 (NN-B loader row)
    const int bnq  = (tid & 15) * 4; // 0..60

    float acc[4][4] = {};

    for (int k0 = 0; k0 < K; k0 += 16) {
        float4 a4 = *(const float4*)&A[(long)(m0 + lrow)*K + k0 + lkq];
        float4 b4;
        if (TRANSB) b4 = *(const float4*)&Bm[(long)(n0 + lrow)*K + k0 + lkq];
        else        b4 = *(const float4*)&Bm[(long)(k0 + brow)*N + n0 + bnq];

        __syncthreads();
        sA[lkq+0][lrow] = a4.x; sA[lkq+1][lrow] = a4.y;
        sA[lkq+2][lrow] = a4.z; sA[lkq+3][lrow] = a4.w;
        if (TRANSB) {
            sB[lkq+0][lrow] = b4.x; sB[lkq+1][lrow] = b4.y;
            sB[lkq+2][lrow] = b4.z; sB[lkq+3][lrow] = b4.w;
        } else {
            *(float4*)&sB[brow][bnq] = b4;
        }
        __syncthreads();

        #pragma unroll
        for (int kk = 0; kk < 16; kk++) {
            float4 av = *(const float4*)&sA[kk][ty*4];
            float4 bv = *(const float4*)&sB[kk][tx*4];
            float ar[4] = {av.x, av.y, av.z, av.w};
            float br[4] = {bv.x, bv.y, bv.z, bv.w};
            #pragma unroll
            for (int i = 0; i < 4; i++)
                #pragma unroll
                for (int j = 0; j < 4; j++)
                    acc[i][j] += ar[i] * br[j];
        }
    }

    #pragma unroll
    for (int i = 0; i < 4; i++) {
        int m = m0 + ty*4 + i;
        int nb = n0 + tx*4;
        float4 c4;
        float cv[4];
        #pragma unroll
        for (int j = 0; j < 4; j++) {
            cv[j] = acc[i][j] * scale;
            if (HASBIAS) cv[j] += bias[nb + j];
        }
        c4.x = cv[0]; c4.y = cv[1]; c4.z = cv[2]; c4.w = cv[3];
        *(float4*)&C[(long)m*N + nb] = c4;
    }
}

// ---------------- masked softmax over rows of g_attn ----------------
__global__ __launch_bounds__(256) void softmax_kernel(const int* __restrict__ valid_len)
{
    int row = blockIdx.x;            // 0 .. B*T-1
    int b   = row >> 9;
    float* s = g_attn + (long)row * NK;
    int vl = valid_len[b];
    int j0 = threadIdx.x, j1 = threadIdx.x + 256;
    float s0 = (j0 < vl) ? s[j0] : -1e9f;
    float s1 = (j1 < vl) ? s[j1] : -1e9f;

    __shared__ float red[32];
    float m   = block_max(fmaxf(s0, s1), red);
    float e0  = __expf(s0 - m);
    float e1  = __expf(s1 - m);
    float sum = block_sum(e0 + e1, red);
    float inv = 1.f / sum;
    s[j0] = e0 * inv;
    s[j1] = e1 * inv;
}

// ---------------- pooled = max_t enc + le ; out = sigmoid(pooled @ w_out + b) --
__global__ __launch_bounds__(256) void pool_out_kernel(
    const int* __restrict__ labels, const float* __restrict__ emb,
    const float* __restrict__ w_out, const float* __restrict__ b_out,
    float* __restrict__ out)
{
    int b = blockIdx.x;
    int d = threadIdx.x;
    const float* e = g_enc + (long)b*TT*DD + d;
    float m = -3.4e38f;
    #pragma unroll 8
    for (int t = 0; t < TT; t++) m = fmaxf(m, e[(long)t*DD]);
    float p = m + emb[labels[b]*DD + d];

    __shared__ float red[32];
    float sum = block_sum(p * w_out[d], red);
    if (threadIdx.x == 0)
        out[b] = 1.f / (1.f + __expf(-(sum + b_out[0])));
}

// ---------------- launch ----------------
extern "C" void kernel_launch(void* const* d_in, const int* in_sizes, int n_in,
                              void* d_out, int out_size)
{
    const float* traj      = (const float*)d_in[0];
    const int*   labels    = (const int*)  d_in[1];
    const float* h         = (const float*)d_in[2];
    const int*   valid_len = (const int*)  d_in[3];
    const float* emb       = (const float*)d_in[4];
    const float* w_mlp     = (const float*)d_in[5];
    const float* b_mlp     = (const float*)d_in[6];
    const float* ln_g      = (const float*)d_in[7];
    const float* ln_b      = (const float*)d_in[8];
    const float* wq        = (const float*)d_in[9];
    const float* bq        = (const float*)d_in[10];
    const float* wk        = (const float*)d_in[11];
    const float* bk        = (const float*)d_in[12];
    const float* wv        = (const float*)d_in[13];
    const float* bv        = (const float*)d_in[14];
    const float* w_out     = (const float*)d_in[15];
    const float* b_out     = (const float*)d_in[16];
    float* out = (float*)d_out;

    float *px, *pq, *pk, *pv, *pattn, *penc;
    cudaGetSymbolAddress((void**)&px,    g_x);
    cudaGetSymbolAddress((void**)&pq,    g_q);
    cudaGetSymbolAddress((void**)&pk,    g_k);
    cudaGetSymbolAddress((void**)&pv,    g_v);
    cudaGetSymbolAddress((void**)&pattn, g_attn);
    cudaGetSymbolAddress((void**)&penc,  g_enc);

    // 1. x = leaky(LN(traj@w_mlp)) + le
    build_x_kernel<<<BB*TT, 256>>>(traj, labels, w_mlp, b_mlp, ln_g, ln_b, emb);

    // 2. q/k/v projections: [32768,256] @ [256,256] + bias
    dim3 gproj(DD/64, (BB*TT)/64, 1);
    gemm_tile_kernel<false,true><<<gproj, 256>>>(px, wq, bq, pq, BB*TT, DD, DD, 0, 0, 0, 1.f);
    gemm_tile_kernel<false,true><<<gproj, 256>>>(h,  wk, bk, pk, BB*NK, DD, DD, 0, 0, 0, 1.f);
    gemm_tile_kernel<false,true><<<gproj, 256>>>(h,  wv, bv, pv, BB*NK, DD, DD, 0, 0, 0, 1.f);

    // 3. scores = q @ k^T / sqrt(D), batched over B
    dim3 gsc(NK/64, TT/64, BB);
    gemm_tile_kernel<true,false><<<gsc, 256>>>(pq, pk, nullptr, pattn, TT, NK, DD,
        (long)TT*DD, (long)NK*DD, (long)TT*NK, 0.0625f);

    // 4. key-masked softmax (in place on g_attn)
    softmax_kernel<<<BB*TT, 256>>>(valid_len);

    // 5. enc = attn @ v, batched over B
    dim3 genc(DD/64, TT/64, BB);
    gemm_tile_kernel<false,false><<<genc, 256>>>(pattn, pv, nullptr, penc, TT, DD, NK,
        (long)TT*NK, (long)NK*DD, (long)TT*DD, 1.f);

    // 6. max-pool over T, +le, dot w_out, sigmoid
    pool_out_kernel<<<BB, 256>>>(labels, emb, w_out, b_out, out);
}

// round 2
// speedup vs baseline: 1.1386x; 1.1386x over previous
#include <cuda_runtime.h>
#include <math.h>

#define BB 64
#define TT 512
#define NK 512
#define DD 256
#define EPSLN 1e-5f

// ---------------- scratch (device globals: alloc-guard-safe) ----------------
__device__ float g_x[BB*TT*DD];
__device__ float g_q[BB*TT*DD];
__device__ float g_k[BB*NK*DD];
__device__ float g_v[BB*NK*DD];
__device__ float g_attn[BB*TT*NK];
__device__ float g_enc[BB*TT*DD];

// ---------------- reductions ----------------
__device__ __forceinline__ float warp_sum(float v) {
    #pragma unroll
    for (int o = 16; o > 0; o >>= 1) v += __shfl_xor_sync(0xffffffffu, v, o);
    return v;
}
__device__ __forceinline__ float warp_max(float v) {
    #pragma unroll
    for (int o = 16; o > 0; o >>= 1) v = fmaxf(v, __shfl_xor_sync(0xffffffffu, v, o));
    return v;
}
__device__ __forceinline__ float block_sum(float v, float* red) {
    int lane = threadIdx.x & 31, wid = threadIdx.x >> 5;
    v = warp_sum(v);
    if (lane == 0) red[wid] = v;
    __syncthreads();
    v = (threadIdx.x < (blockDim.x >> 5)) ? red[threadIdx.x] : 0.f;
    if (wid == 0) v = warp_sum(v);
    if (threadIdx.x == 0) red[0] = v;
    __syncthreads();
    v = red[0];
    __syncthreads();
    return v;
}
__device__ __forceinline__ float block_max(float v, float* red) {
    int lane = threadIdx.x & 31, wid = threadIdx.x >> 5;
    v = warp_max(v);
    if (lane == 0) red[wid] = v;
    __syncthreads();
    v = (threadIdx.x < (blockDim.x >> 5)) ? red[threadIdx.x] : -3.4e38f;
    if (wid == 0) v = warp_max(v);
    if (threadIdx.x == 0) red[0] = v;
    __syncthreads();
    v = red[0];
    __syncthreads();
    return v;
}

// ---------------- x = leaky(LN(traj@w_mlp + b)) + emb[labels] ----------------
__global__ __launch_bounds__(256) void build_x_kernel(
    const float* __restrict__ traj, const int* __restrict__ labels,
    const float* __restrict__ w_mlp, const float* __restrict__ b_mlp,
    const float* __restrict__ ln_g, const float* __restrict__ ln_b,
    const float* __restrict__ emb)
{
    int row = blockIdx.x;            // 0 .. B*T-1
    int b   = row >> 9;              // T = 512
    int d   = threadIdx.x;           // 0 .. 255
    float t0 = traj[row*2 + 0];
    float t1 = traj[row*2 + 1];
    float v  = t0 * w_mlp[d] + t1 * w_mlp[DD + d] + b_mlp[d];

    __shared__ float red[32];
    float mean = block_sum(v, red) * (1.f/DD);
    float dv   = v - mean;
    float var  = block_sum(dv*dv, red) * (1.f/DD);
    float y = dv * rsqrtf(var + EPSLN) * ln_g[d] + ln_b[d];
    y = (y > 0.f) ? y : 0.01f * y;   // leaky_relu default slope
    g_x[(long)row*DD + d] = y + emb[labels[b]*DD + d];
}

// ---------------- 128x128x16 SGEMM, 8x8 micro-tile, double-buffered ----------
// C[M,N] = scale * (A[M,K] @ op(B)) (+ bias[n]); op(B)=B[K,N] (NN) or B[N,K]^T (NT)
// 256 threads. Batched via blockIdx.z. All of M,N multiples of 128; K mult of 16.
template<bool TRANSB, bool HASBIAS>
__global__ __launch_bounds__(256) void gemm128_kernel(
    const float* __restrict__ A, const float* __restrict__ Bm,
    const float* __restrict__ bias, float* __restrict__ C,
    int M, int N, int K, long strA, long strB, long strC, float scale)
{
    A  += (long)blockIdx.z * strA;
    Bm += (long)blockIdx.z * strB;
    C  += (long)blockIdx.z * strC;
    const int m0 = blockIdx.y * 128;
    const int n0 = blockIdx.x * 128;

    __shared__ float sA[2][16][128];
    __shared__ float sB[2][16][128];

    const int tid = threadIdx.x;
    const int tx  = tid & 15;        // n micro-block (tx*8)
    const int ty  = tid >> 4;        // m micro-block (ty*8)

    // A loader (and NT-B loader): row = tid>>1 (0..127), k-col = (tid&1)*8 (+0,+4)
    const int lr  = tid >> 1;
    const int lc  = (tid & 1) * 8;
    // NN-B loader: row = tid>>4 (0..15), n-col = (tid&15)*4 (+0,+64)
    const int nbr = tid >> 4;
    const int nbc = (tid & 15) * 4;

    const float* Aptr  = A + (long)(m0 + lr) * K + lc;
    const float* BptrT = Bm + (long)(n0 + lr) * K + lc;        // NT
    const float* BptrN = Bm + (long)nbr * N + n0 + nbc;        // NN

    float acc[8][8] = {};

    // ---- preload tile 0 ----
    float4 a0 = *(const float4*)(Aptr);
    float4 a1 = *(const float4*)(Aptr + 4);
    float4 b0, b1;
    if (TRANSB) { b0 = *(const float4*)(BptrT); b1 = *(const float4*)(BptrT + 4); }
    else        { b0 = *(const float4*)(BptrN); b1 = *(const float4*)(BptrN + 64); }

    sA[0][lc+0][lr] = a0.x; sA[0][lc+1][lr] = a0.y; sA[0][lc+2][lr] = a0.z; sA[0][lc+3][lr] = a0.w;
    sA[0][lc+4][lr] = a1.x; sA[0][lc+5][lr] = a1.y; sA[0][lc+6][lr] = a1.z; sA[0][lc+7][lr] = a1.w;
    if (TRANSB) {
        sB[0][lc+0][lr] = b0.x; sB[0][lc+1][lr] = b0.y; sB[0][lc+2][lr] = b0.z; sB[0][lc+3][lr] = b0.w;
        sB[0][lc+4][lr] = b1.x; sB[0][lc+5][lr] = b1.y; sB[0][lc+6][lr] = b1.z; sB[0][lc+7][lr] = b1.w;
    } else {
        *(float4*)&sB[0][nbr][nbc]      = b0;
        *(float4*)&sB[0][nbr][nbc + 64] = b1;
    }
    __syncthreads();

    const int ntiles = K >> 4;
    int buf = 0;
    for (int t = 1; t < ntiles; t++) {
        // issue next-tile global loads early
        const float* Ap = Aptr + t*16;
        a0 = *(const float4*)(Ap);
        a1 = *(const float4*)(Ap + 4);
        if (TRANSB) {
            const float* Bp = BptrT + t*16;
            b0 = *(const float4*)(Bp); b1 = *(const float4*)(Bp + 4);
        } else {
            const float* Bp = BptrN + (long)t*16*N;
            b0 = *(const float4*)(Bp); b1 = *(const float4*)(Bp + 64);
        }

        // compute on current buffer
        #pragma unroll
        for (int kk = 0; kk < 16; kk++) {
            float4 av0 = *(const float4*)&sA[buf][kk][ty*8];
            float4 av1 = *(const float4*)&sA[buf][kk][ty*8 + 4];
            float4 bv0 = *(const float4*)&sB[buf][kk][tx*8];
            float4 bv1 = *(const float4*)&sB[buf][kk][tx*8 + 4];
            float ar[8] = {av0.x,av0.y,av0.z,av0.w,av1.x,av1.y,av1.z,av1.w};
            float br[8] = {bv0.x,bv0.y,bv0.z,bv0.w,bv1.x,bv1.y,bv1.z,bv1.w};
            #pragma unroll
            for (int i = 0; i < 8; i++)
                #pragma unroll
                for (int j = 0; j < 8; j++)
                    acc[i][j] += ar[i] * br[j];
        }

        // stage into the other buffer (no sync needed: disjoint from compute buf)
        int nb = buf ^ 1;
        sA[nb][lc+0][lr] = a0.x; sA[nb][lc+1][lr] = a0.y; sA[nb][lc+2][lr] = a0.z; sA[nb][lc+3][lr] = a0.w;
        sA[nb][lc+4][lr] = a1.x; sA[nb][lc+5][lr] = a1.y; sA[nb][lc+6][lr] = a1.z; sA[nb][lc+7][lr] = a1.w;
        if (TRANSB) {
            sB[nb][lc+0][lr] = b0.x; sB[nb][lc+1][lr] = b0.y; sB[nb][lc+2][lr] = b0.z; sB[nb][lc+3][lr] = b0.w;
            sB[nb][lc+4][lr] = b1.x; sB[nb][lc+5][lr] = b1.y; sB[nb][lc+6][lr] = b1.z; sB[nb][lc+7][lr] = b1.w;
        } else {
            *(float4*)&sB[nb][nbr][nbc]      = b0;
            *(float4*)&sB[nb][nbr][nbc + 64] = b1;
        }
        __syncthreads();
        buf = nb;
    }

    // last tile
    #pragma unroll
    for (int kk = 0; kk < 16; kk++) {
        float4 av0 = *(const float4*)&sA[buf][kk][ty*8];
        float4 av1 = *(const float4*)&sA[buf][kk][ty*8 + 4];
        float4 bv0 = *(const float4*)&sB[buf][kk][tx*8];
        float4 bv1 = *(const float4*)&sB[buf][kk][tx*8 + 4];
        float ar[8] = {av0.x,av0.y,av0.z,av0.w,av1.x,av1.y,av1.z,av1.w};
        float br[8] = {bv0.x,bv0.y,bv0.z,bv0.w,bv1.x,bv1.y,bv1.z,bv1.w};
        #pragma unroll
        for (int i = 0; i < 8; i++)
            #pragma unroll
            for (int j = 0; j < 8; j++)
                acc[i][j] += ar[i] * br[j];
    }

    // epilogue
    float bj0[4], bj1[4];
    if (HASBIAS) {
        *(float4*)bj0 = *(const float4*)&bias[n0 + tx*8];
        *(float4*)bj1 = *(const float4*)&bias[n0 + tx*8 + 4];
    }
    #pragma unroll
    for (int i = 0; i < 8; i++) {
        int m  = m0 + ty*8 + i;
        int nb = n0 + tx*8;
        float4 c0, c1;
        c0.x = acc[i][0]*scale; c0.y = acc[i][1]*scale; c0.z = acc[i][2]*scale; c0.w = acc[i][3]*scale;
        c1.x = acc[i][4]*scale; c1.y = acc[i][5]*scale; c1.z = acc[i][6]*scale; c1.w = acc[i][7]*scale;
        if (HASBIAS) {
            c0.x += bj0[0]; c0.y += bj0[1]; c0.z += bj0[2]; c0.w += bj0[3];
            c1.x += bj1[0]; c1.y += bj1[1]; c1.z += bj1[2]; c1.w += bj1[3];
        }
        *(float4*)&C[(long)m*N + nb]     = c0;
        *(float4*)&C[(long)m*N + nb + 4] = c1;
    }
}

// ---------------- masked softmax over rows of g_attn ----------------
__global__ __launch_bounds__(256) void softmax_kernel(const int* __restrict__ valid_len)
{
    int row = blockIdx.x;            // 0 .. B*T-1
    int b   = row >> 9;
    float* s = g_attn + (long)row * NK;
    int vl = valid_len[b];
    int j0 = threadIdx.x, j1 = threadIdx.x + 256;
    float s0 = (j0 < vl) ? s[j0] : -1e9f;
    float s1 = (j1 < vl) ? s[j1] : -1e9f;

    __shared__ float red[32];
    float m   = block_max(fmaxf(s0, s1), red);
    float e0  = __expf(s0 - m);
    float e1  = __expf(s1 - m);
    float sum = block_sum(e0 + e1, red);
    float inv = 1.f / sum;
    s[j0] = e0 * inv;
    s[j1] = e1 * inv;
}

// ---------------- pooled = max_t enc + le ; out = sigmoid(pooled @ w_out + b) --
__global__ __launch_bounds__(256) void pool_out_kernel(
    const int* __restrict__ labels, const float* __restrict__ emb,
    const float* __restrict__ w_out, const float* __restrict__ b_out,
    float* __restrict__ out)
{
    int b = blockIdx.x;
    int d = threadIdx.x;
    const float* e = g_enc + (long)b*TT*DD + d;
    float m = -3.4e38f;
    #pragma unroll 8
    for (int t = 0; t < TT; t++) m = fmaxf(m, e[(long)t*DD]);
    float p = m + emb[labels[b]*DD + d];

    __shared__ float red[32];
    float sum = block_sum(p * w_out[d], red);
    if (threadIdx.x == 0)
        out[b] = 1.f / (1.f + __expf(-(sum + b_out[0])));
}

// ---------------- launch ----------------
extern "C" void kernel_launch(void* const* d_in, const int* in_sizes, int n_in,
                              void* d_out, int out_size)
{
    const float* traj      = (const float*)d_in[0];
    const int*   labels    = (const int*)  d_in[1];
    const float* h         = (const float*)d_in[2];
    const int*   valid_len = (const int*)  d_in[3];
    const float* emb       = (const float*)d_in[4];
    const float* w_mlp     = (const float*)d_in[5];
    const float* b_mlp     = (const float*)d_in[6];
    const float* ln_g      = (const float*)d_in[7];
    const float* ln_b      = (const float*)d_in[8];
    const float* wq        = (const float*)d_in[9];
    const float* bq        = (const float*)d_in[10];
    const float* wk        = (const float*)d_in[11];
    const float* bk        = (const float*)d_in[12];
    const float* wv        = (const float*)d_in[13];
    const float* bv        = (const float*)d_in[14];
    const float* w_out     = (const float*)d_in[15];
    const float* b_out     = (const float*)d_in[16];
    float* out = (float*)d_out;

    float *px, *pq, *pk, *pv, *pattn, *penc;
    cudaGetSymbolAddress((void**)&px,    g_x);
    cudaGetSymbolAddress((void**)&pq,    g_q);
    cudaGetSymbolAddress((void**)&pk,    g_k);
    cudaGetSymbolAddress((void**)&pv,    g_v);
    cudaGetSymbolAddress((void**)&pattn, g_attn);
    cudaGetSymbolAddress((void**)&penc,  g_enc);

    // 1. x = leaky(LN(traj@w_mlp)) + le
    build_x_kernel<<<BB*TT, 256>>>(traj, labels, w_mlp, b_mlp, ln_g, ln_b, emb);

    // 2. q/k/v projections: [32768,256] @ [256,256] + bias
    dim3 gproj(DD/128, (BB*TT)/128, 1);
    gemm128_kernel<false,true><<<gproj, 256>>>(px, wq, bq, pq, BB*TT, DD, DD, 0, 0, 0, 1.f);
    gemm128_kernel<false,true><<<gproj, 256>>>(h,  wk, bk, pk, BB*NK, DD, DD, 0, 0, 0, 1.f);
    gemm128_kernel<false,true><<<gproj, 256>>>(h,  wv, bv, pv, BB*NK, DD, DD, 0, 0, 0, 1.f);

    // 3. scores = q @ k^T / sqrt(D), batched over B
    dim3 gsc(NK/128, TT/128, BB);
    gemm128_kernel<true,false><<<gsc, 256>>>(pq, pk, nullptr, pattn, TT, NK, DD,
        (long)TT*DD, (long)NK*DD, (long)TT*NK, 0.0625f);

    // 4. key-masked softmax (in place on g_attn)
    softmax_kernel<<<BB*TT, 256>>>(valid_len);

    // 5. enc = attn @ v, batched over B
    dim3 genc(DD/128, TT/128, BB);
    gemm128_kernel<false,false><<<genc, 256>>>(pattn, pv, nullptr, penc, TT, DD, NK,
        (long)TT*NK, (long)NK*DD, (long)TT*DD, 1.f);

    // 6. max-pool over T, +le, dot w_out, sigmoid
    pool_out_kernel<<<BB, 256>>>(labels, emb, w_out, b_out, out);
}

// round 5
// speedup vs baseline: 1.8782x; 1.6495x over previous
#include <cuda_runtime.h>
#include <cuda_bf16.h>
#include <cstdint>
#include <math.h>

#define BB 64
#define TT 512
#define NKV 512
#define DD 256
#define MTOT (BB*TT)
#define EPSLN 1e-5f

// ======================= scratch (device globals) ===========================
__device__ __align__(256) __nv_bfloat16 g_xh[MTOT*DD], g_xl[MTOT*DD];
__device__ __align__(256) __nv_bfloat16 g_hh[MTOT*DD], g_hl[MTOT*DD];
__device__ __align__(256) __nv_bfloat16 g_wqth[DD*DD], g_wqtl[DD*DD];
__device__ __align__(256) __nv_bfloat16 g_wkth[DD*DD], g_wktl[DD*DD];
__device__ __align__(256) __nv_bfloat16 g_wvth[DD*DD], g_wvtl[DD*DD];
__device__ __align__(256) __nv_bfloat16 g_qh[MTOT*DD], g_ql[MTOT*DD];
__device__ __align__(256) __nv_bfloat16 g_kh[MTOT*DD], g_kl[MTOT*DD];
__device__ __align__(256) __nv_bfloat16 g_vth[BB*DD*NKV], g_vtl[BB*DD*NKV];
__device__ __align__(256) __nv_bfloat16 g_ath[BB*TT*NKV], g_atl[BB*TT*NKV];
__device__ __align__(256) float g_sc[BB*TT*NKV];
__device__ __align__(256) float g_enc[MTOT*DD];

// ======================= PTX helpers (baseline ISA only) ====================
__device__ __forceinline__ uint32_t smem_to_u32(const void* p) {
    uint32_t a;
    asm("{ .reg .u64 t; cvta.to.shared.u64 t, %1; cvt.u32.u64 %0, t; }" : "=r"(a) : "l"(p));
    return a;
}
#define CP_ASYNC16(dst_u32, src_ptr) \
    asm volatile("cp.async.cg.shared.global [%0], [%1], 16;" \
        :: "r"(dst_u32), "l"(src_ptr))
#define CP_ASYNC_COMMIT() asm volatile("cp.async.commit_group;" ::: "memory")
#define CP_ASYNC_WAIT0()  asm volatile("cp.async.wait_group 0;" ::: "memory")
#define CP_ASYNC_WAIT1()  asm volatile("cp.async.wait_group 1;" ::: "memory")

__device__ __forceinline__ void ldsm4(uint32_t* r, uint32_t addr) {
    asm volatile("ldmatrix.sync.aligned.m8n8.x4.shared.b16 {%0,%1,%2,%3}, [%4];"
        : "=r"(r[0]), "=r"(r[1]), "=r"(r[2]), "=r"(r[3]) : "r"(addr));
}
// D(f32) += A(bf16 m16k16 row) * B(bf16 k16n8 col)
__device__ __forceinline__ void mma_bf16(float* c, const uint32_t* a, const uint32_t* b) {
    asm volatile(
        "mma.sync.aligned.m16n8k16.row.col.f32.bf16.bf16.f32 "
        "{%0,%1,%2,%3}, {%4,%5,%6,%7}, {%8,%9}, {%0,%1,%2,%3};"
        : "+f"(c[0]), "+f"(c[1]), "+f"(c[2]), "+f"(c[3])
        : "r"(a[0]), "r"(a[1]), "r"(a[2]), "r"(a[3]), "r"(b[0]), "r"(b[1]));
}

// =============== hi/lo pair split ===========================================
__device__ __forceinline__ void split_pair(float v, __nv_bfloat16& h, __nv_bfloat16& l) {
    h = __float2bfloat16(v);
    l = __float2bfloat16(v - __bfloat162float(h));
}

// ======================= reductions =========================================
__device__ __forceinline__ float warp_sum(float v) {
    #pragma unroll
    for (int o = 16; o > 0; o >>= 1) v += __shfl_xor_sync(0xffffffffu, v, o);
    return v;
}
__device__ __forceinline__ float warp_max(float v) {
    #pragma unroll
    for (int o = 16; o > 0; o >>= 1) v = fmaxf(v, __shfl_xor_sync(0xffffffffu, v, o));
    return v;
}
__device__ __forceinline__ float block_sum(float v, float* red) {
    int lane = threadIdx.x & 31, wid = threadIdx.x >> 5;
    v = warp_sum(v);
    if (lane == 0) red[wid] = v;
    __syncthreads();
    v = (threadIdx.x < (blockDim.x >> 5)) ? red[threadIdx.x] : 0.f;
    if (wid == 0) v = warp_sum(v);
    if (threadIdx.x == 0) red[0] = v;
    __syncthreads();
    v = red[0];
    __syncthreads();
    return v;
}
__device__ __forceinline__ float block_max(float v, float* red) {
    int lane = threadIdx.x & 31, wid = threadIdx.x >> 5;
    v = warp_max(v);
    if (lane == 0) red[wid] = v;
    __syncthreads();
    v = (threadIdx.x < (blockDim.x >> 5)) ? red[threadIdx.x] : -3.4e38f;
    if (wid == 0) v = warp_max(v);
    if (threadIdx.x == 0) red[0] = v;
    __syncthreads();
    v = red[0];
    __syncthreads();
    return v;
}

// ======================= elementwise kernels ================================
__global__ __launch_bounds__(256) void build_x_pair_kernel(
    const float* __restrict__ traj, const int* __restrict__ labels,
    const float* __restrict__ w_mlp, const float* __restrict__ b_mlp,
    const float* __restrict__ ln_g, const float* __restrict__ ln_b,
    const float* __restrict__ emb)
{
    int row = blockIdx.x;
    int b   = row >> 9;
    int d   = threadIdx.x;
    float t0 = traj[row*2 + 0];
    float t1 = traj[row*2 + 1];
    float v  = t0 * w_mlp[d] + t1 * w_mlp[DD + d] + b_mlp[d];

    __shared__ float red[32];
    float mean = block_sum(v, red) * (1.f/DD);
    float dv   = v - mean;
    float var  = block_sum(dv*dv, red) * (1.f/DD);
    float y = dv * rsqrtf(var + EPSLN) * ln_g[d] + ln_b[d];
    y = (y > 0.f) ? y : 0.01f * y;
    float xv = y + emb[labels[b]*DD + d];
    __nv_bfloat16 hv, lv; split_pair(xv, hv, lv);
    g_xh[(long)row*DD + d] = hv;
    g_xl[(long)row*DD + d] = lv;
}

__global__ __launch_bounds__(256) void conv_pair4_kernel(
    const float* __restrict__ in, __nv_bfloat16* __restrict__ oh,
    __nv_bfloat16* __restrict__ ol, int n4)
{
    int i = blockIdx.x*256 + threadIdx.x;
    if (i >= n4) return;
    float4 v = ((const float4*)in)[i];
    float f[4] = {v.x, v.y, v.z, v.w};
    uint32_t hs[4], ls[4];
    #pragma unroll
    for (int j = 0; j < 4; j++) {
        __nv_bfloat16 hv, lv; split_pair(f[j], hv, lv);
        hs[j] = __bfloat16_as_ushort(hv);
        ls[j] = __bfloat16_as_ushort(lv);
    }
    ((uint2*)oh)[i] = make_uint2(hs[0] | (hs[1]<<16), hs[2] | (hs[3]<<16));
    ((uint2*)ol)[i] = make_uint2(ls[0] | (ls[1]<<16), ls[2] | (ls[3]<<16));
}

// w[k][n] (256x256) -> wT[n][k] pair
__global__ __launch_bounds__(256) void convT_pair_kernel(
    const float* __restrict__ w, __nv_bfloat16* __restrict__ oh,
    __nv_bfloat16* __restrict__ ol)
{
    int n = blockIdx.x, k = threadIdx.x;
    float v = w[k*DD + n];
    __nv_bfloat16 hv, lv; split_pair(v, hv, lv);
    oh[n*DD + k] = hv;
    ol[n*DD + k] = lv;
}

__global__ __launch_bounds__(256) void softmax_pair_kernel(const int* __restrict__ valid_len)
{
    int row = blockIdx.x;
    int b   = row >> 9;
    const float* s = g_sc + (long)row * NKV;
    int vl = valid_len[b];
    int j0 = threadIdx.x, j1 = threadIdx.x + 256;
    float s0 = (j0 < vl) ? s[j0] : -1e9f;
    float s1 = (j1 < vl) ? s[j1] : -1e9f;

    __shared__ float red[32];
    float m   = block_max(fmaxf(s0, s1), red);
    float e0  = __expf(s0 - m);
    float e1  = __expf(s1 - m);
    float sum = block_sum(e0 + e1, red);
    float inv = 1.f / sum;
    float p0 = e0 * inv, p1 = e1 * inv;
    __nv_bfloat16 hv, lv;
    split_pair(p0, hv, lv);
    g_ath[(long)row*NKV + j0] = hv; g_atl[(long)row*NKV + j0] = lv;
    split_pair(p1, hv, lv);
    g_ath[(long)row*NKV + j1] = hv; g_atl[(long)row*NKV + j1] = lv;
}

__global__ __launch_bounds__(256) void pool_out_kernel(
    const int* __restrict__ labels, const float* __restrict__ emb,
    const float* __restrict__ w_out, const float* __restrict__ b_out,
    float* __restrict__ out)
{
    int b = blockIdx.x;
    int d = threadIdx.x;
    const float* e = g_enc + (long)b*TT*DD + d;
    float m = -3.4e38f;
    #pragma unroll 8
    for (int t = 0; t < TT; t++) m = fmaxf(m, e[(long)t*DD]);
    float p = m + emb[labels[b]*DD + d];

    __shared__ float red[32];
    float sum = block_sum(p * w_out[d], red);
    if (threadIdx.x == 0)
        out[b] = 1.f / (1.f + __expf(-(sum + b_out[0])));
}

// ======================= mma.sync pair GEMM =================================
// C = scale * sum_K (Ah+Al)[m,k]*(Bh+Bl)[n,k]   (Al*Bl dropped)
// A: [M,K] K-major bf16 pair;  B: [Nglob,K] K-major bf16 pair.
// MODE 0: Cf = D*scale (fp32). MODE 1: pair out + bias[n]. MODE 2: pair out + bias[m].
// Block tile 128x128, K-chunk 32, 8 warps (2m x 4n), warp tile 64x32.
// SMEM rows padded to 40 bf16 (80B) for conflict-free ldmatrix.
#define LDS_ROW  80                  // bytes per padded smem row (32 bf16 + pad)
#define TILE_SB  (128*LDS_ROW)       // 10240 B per tile
#define STAGE_SB (4*TILE_SB)         // Ah, Al, Bh, Bl
#define SMEM_REQ (2*STAGE_SB)        // 81920 B

template<int MODE>
__global__ __launch_bounds__(256, 1) void mma_gemm_kernel(
    const __nv_bfloat16* __restrict__ Ah, const __nv_bfloat16* __restrict__ Al,
    const __nv_bfloat16* __restrict__ Bh, const __nv_bfloat16* __restrict__ Bl,
    const float* __restrict__ bias,
    float* __restrict__ Cf, __nv_bfloat16* __restrict__ Ch, __nv_bfloat16* __restrict__ Cl,
    int N, int K, long sA, long sB, long sC, float scale)
{
    extern __shared__ char dsm[];
    const uint32_t sm0 = smem_to_u32(dsm);

    const int tid  = threadIdx.x;
    const int lane = tid & 31;
    const int w    = tid >> 5;
    const int wm   = w & 1;          // 0..1 -> m offset wm*64
    const int wn   = w >> 1;         // 0..3 -> n offset wn*32

    Ah += (long)blockIdx.z * sA;  Al += (long)blockIdx.z * sA;
    Bh += (long)blockIdx.z * sB;  Bl += (long)blockIdx.z * sB;
    const long czoff = (long)blockIdx.z * sC;
    const int m0 = blockIdx.y * 128;
    const int n0 = blockIdx.x * 128;

    float acc[4][4][4] = {};

    const __nv_bfloat16* tp[4] = {Ah, Al, Bh, Bl};

    auto prefetch = [&](int c) {
        const int kc = c << 5;
        const uint32_t sb = sm0 + (c & 1) * STAGE_SB;
        #pragma unroll
        for (int t = 0; t < 8; t++) {
            int idx  = t*256 + tid;          // 0..2047
            int tile = idx >> 9;             // 0..3
            int cc   = idx & 511;            // chunk within tile
            int row  = cc >> 2;              // 0..127
            int seg  = cc & 3;               // 0..3 (16B each)
            int base = (tile < 2) ? m0 : n0;
            const __nv_bfloat16* src = tp[tile] + (long)(base + row)*K + kc + seg*8;
            uint32_t dst = sb + tile*TILE_SB + row*LDS_ROW + seg*16;
            CP_ASYNC16(dst, src);
        }
        CP_ASYNC_COMMIT();
    };

    const int nch = K >> 5;
    prefetch(0);
    for (int c = 0; c < nch; c++) {
        if (c + 1 < nch) { prefetch(c + 1); CP_ASYNC_WAIT1(); }
        else             { CP_ASYNC_WAIT0(); }
        __syncthreads();

        const uint32_t sb = sm0 + (c & 1) * STAGE_SB;
        #pragma unroll
        for (int ks = 0; ks < 2; ks++) {
            uint32_t aH[4][4], aL[4][4], bH[4][2], bL[4][2];
            // --- A fragments: m16k16 via ldmatrix.x4 ---
            // lane -> row m + (lane&15), col k0 + ((lane>>4)&1)*8
            {
                const int arow = wm*64 + (lane & 15);
                const int acol = (ks*16 + ((lane >> 4) & 1)*8) * 2;
                #pragma unroll
                for (int mt = 0; mt < 4; mt++) {
                    uint32_t ad = sb + (arow + mt*16)*LDS_ROW + acol;
                    ldsm4(aH[mt], ad);                 // Ah tile at offset 0
                    ldsm4(aL[mt], ad + TILE_SB);       // Al tile
                }
            }
            // --- B fragments: k16n16 via ldmatrix.x4 (two n8 tiles per load) ---
            // lane -> row n + ((lane>>4)&1)*8 + (lane&7), col k0 + ((lane>>3)&1)*8
            {
                const int bcol = (ks*16 + ((lane >> 3) & 1)*8) * 2;
                #pragma unroll
                for (int g = 0; g < 2; g++) {
                    const int brow = wn*32 + g*16 + ((lane >> 4) & 1)*8 + (lane & 7);
                    uint32_t bd = sb + 2*TILE_SB + brow*LDS_ROW + bcol;
                    uint32_t t4[4];
                    ldsm4(t4, bd);                     // Bh
                    bH[2*g+0][0] = t4[0]; bH[2*g+0][1] = t4[1];
                    bH[2*g+1][0] = t4[2]; bH[2*g+1][1] = t4[3];
                    ldsm4(t4, bd + TILE_SB);           // Bl
                    bL[2*g+0][0] = t4[0]; bL[2*g+0][1] = t4[1];
                    bL[2*g+1][0] = t4[2]; bL[2*g+1][1] = t4[3];
                }
            }
            // --- 3-product pair MMA ---
            #pragma unroll
            for (int mt = 0; mt < 4; mt++)
                #pragma unroll
                for (int nt = 0; nt < 4; nt++) {
                    mma_bf16(acc[mt][nt], aH[mt], bH[nt]);
                    mma_bf16(acc[mt][nt], aH[mt], bL[nt]);
                    mma_bf16(acc[mt][nt], aL[mt], bH[nt]);
                }
        }
        __syncthreads();   // stage (c&1) free for prefetch(c+2)
    }

    // ======================= epilogue =======================================
    #pragma unroll
    for (int mt = 0; mt < 4; mt++) {
        #pragma unroll
        for (int nt = 0; nt < 4; nt++) {
            int mg = m0 + wm*64 + mt*16 + (lane >> 2);
            int ng = n0 + wn*32 + nt*8 + (lane & 3)*2;
            float v0 = acc[mt][nt][0], v1 = acc[mt][nt][1];
            float v2 = acc[mt][nt][2], v3 = acc[mt][nt][3];
            if (MODE == 0) {
                float2 p0 = make_float2(v0*scale, v1*scale);
                float2 p1 = make_float2(v2*scale, v3*scale);
                *(float2*)&Cf[czoff + (long)mg*N + ng]     = p0;
                *(float2*)&Cf[czoff + (long)(mg+8)*N + ng] = p1;
            } else {
                if (MODE == 1) {
                    float b0 = bias[ng], b1 = bias[ng+1];
                    v0 += b0; v1 += b1; v2 += b0; v3 += b1;
                } else {
                    float b0 = bias[mg], b1 = bias[mg+8];
                    v0 += b0; v1 += b0; v2 += b1; v3 += b1;
                }
                __nv_bfloat16 h0,l0,h1,l1,h2,l2,h3,l3;
                split_pair(v0,h0,l0); split_pair(v1,h1,l1);
                split_pair(v2,h2,l2); split_pair(v3,h3,l3);
                uint32_t hw0 = (uint32_t)__bfloat16_as_ushort(h0) | ((uint32_t)__bfloat16_as_ushort(h1) << 16);
                uint32_t lw0 = (uint32_t)__bfloat16_as_ushort(l0) | ((uint32_t)__bfloat16_as_ushort(l1) << 16);
                uint32_t hw1 = (uint32_t)__bfloat16_as_ushort(h2) | ((uint32_t)__bfloat16_as_ushort(h3) << 16);
                uint32_t lw1 = (uint32_t)__bfloat16_as_ushort(l2) | ((uint32_t)__bfloat16_as_ushort(l3) << 16);
                *(uint32_t*)&Ch[czoff + (long)mg*N + ng]     = hw0;
                *(uint32_t*)&Cl[czoff + (long)mg*N + ng]     = lw0;
                *(uint32_t*)&Ch[czoff + (long)(mg+8)*N + ng] = hw1;
                *(uint32_t*)&Cl[czoff + (long)(mg+8)*N + ng] = lw1;
            }
        }
    }
}

// ======================= launch =============================================
extern "C" void kernel_launch(void* const* d_in, const int* in_sizes, int n_in,
                              void* d_out, int out_size)
{
    const float* traj      = (const float*)d_in[0];
    const int*   labels    = (const int*)  d_in[1];
    const float* h         = (const float*)d_in[2];
    const int*   valid_len = (const int*)  d_in[3];
    const float* emb       = (const float*)d_in[4];
    const float* w_mlp     = (const float*)d_in[5];
    const float* b_mlp     = (const float*)d_in[6];
    const float* ln_g      = (const float*)d_in[7];
    const float* ln_b      = (const float*)d_in[8];
    const float* wq        = (const float*)d_in[9];
    const float* bq        = (const float*)d_in[10];
    const float* wk        = (const float*)d_in[11];
    const float* bk        = (const float*)d_in[12];
    const float* wv        = (const float*)d_in[13];
    const float* bv        = (const float*)d_in[14];
    const float* w_out     = (const float*)d_in[15];
    const float* b_out     = (const float*)d_in[16];
    float* out = (float*)d_out;

    cudaFuncSetAttribute(mma_gemm_kernel<0>, cudaFuncAttributeMaxDynamicSharedMemorySize, SMEM_REQ);
    cudaFuncSetAttribute(mma_gemm_kernel<1>, cudaFuncAttributeMaxDynamicSharedMemorySize, SMEM_REQ);
    cudaFuncSetAttribute(mma_gemm_kernel<2>, cudaFuncAttributeMaxDynamicSharedMemorySize, SMEM_REQ);

    __nv_bfloat16 *pxh, *pxl, *phh, *phl, *pwqth, *pwqtl, *pwkth, *pwktl, *pwvth, *pwvtl;
    __nv_bfloat16 *pqh, *pql, *pkh, *pkl, *pvth, *pvtl, *path, *patl;
    float *psc, *penc;
    cudaGetSymbolAddress((void**)&pxh,   g_xh);   cudaGetSymbolAddress((void**)&pxl,   g_xl);
    cudaGetSymbolAddress((void**)&phh,   g_hh);   cudaGetSymbolAddress((void**)&phl,   g_hl);
    cudaGetSymbolAddress((void**)&pwqth, g_wqth); cudaGetSymbolAddress((void**)&pwqtl, g_wqtl);
    cudaGetSymbolAddress((void**)&pwkth, g_wkth); cudaGetSymbolAddress((void**)&pwktl, g_wktl);
    cudaGetSymbolAddress((void**)&pwvth, g_wvth); cudaGetSymbolAddress((void**)&pwvtl, g_wvtl);
    cudaGetSymbolAddress((void**)&pqh,   g_qh);   cudaGetSymbolAddress((void**)&pql,   g_ql);
    cudaGetSymbolAddress((void**)&pkh,   g_kh);   cudaGetSymbolAddress((void**)&pkl,   g_kl);
    cudaGetSymbolAddress((void**)&pvth,  g_vth);  cudaGetSymbolAddress((void**)&pvtl,  g_vtl);
    cudaGetSymbolAddress((void**)&path,  g_ath);  cudaGetSymbolAddress((void**)&patl,  g_atl);
    cudaGetSymbolAddress((void**)&psc,   g_sc);   cudaGetSymbolAddress((void**)&penc,  g_enc);

    // 1. x pair = leaky(LN(traj@w_mlp)) + le
    build_x_pair_kernel<<<MTOT, 256>>>(traj, labels, w_mlp, b_mlp, ln_g, ln_b, emb);
    // 2. h pair
    conv_pair4_kernel<<<(MTOT*DD/4 + 255)/256, 256>>>(h, phh, phl, MTOT*DD/4);
    // 3. transposed weight pairs
    convT_pair_kernel<<<DD, DD>>>(wq, pwqth, pwqtl);
    convT_pair_kernel<<<DD, DD>>>(wk, pwkth, pwktl);
    convT_pair_kernel<<<DD, DD>>>(wv, pwvth, pwvtl);

    // 4. q = x@wq + bq  (pair out, col bias)   M=32768, N=256, K=256
    mma_gemm_kernel<1><<<dim3(2, 256, 1), 256, SMEM_REQ>>>(
        pxh, pxl, pwqth, pwqtl, bq, nullptr, pqh, pql, DD, DD, 0, 0, 0, 1.f);
    // 5. k = h@wk + bk
    mma_gemm_kernel<1><<<dim3(2, 256, 1), 256, SMEM_REQ>>>(
        phh, phl, pwkth, pwktl, bk, nullptr, pkh, pkl, DD, DD, 0, 0, 0, 1.f);
    // 6. vT[b][d][n] = wvT @ h^T + bv[d]  (pair out, row bias)  M=256, N=512, K=256
    mma_gemm_kernel<2><<<dim3(4, 2, BB), 256, SMEM_REQ>>>(
        pwvth, pwvtl, phh, phl, bv, nullptr, pvth, pvtl, NKV, DD,
        0, (long)NKV*DD, (long)DD*NKV, 1.f);
    // 7. scores = q@k^T / 16  (fp32 out)  per-batch M=512, N=512, K=256
    mma_gemm_kernel<0><<<dim3(4, 4, BB), 256, SMEM_REQ>>>(
        pqh, pql, pkh, pkl, nullptr, psc, nullptr, nullptr, NKV, DD,
        (long)TT*DD, (long)NKV*DD, (long)TT*NKV, 0.0625f);
    // 8. masked softmax -> attn pair
    softmax_pair_kernel<<<BB*TT, 256>>>(valid_len);
    // 9. enc = attn@v  (fp32 out)  per-batch M=512, N=256, K=512
    mma_gemm_kernel<0><<<dim3(2, 4, BB), 256, SMEM_REQ>>>(
        path, patl, pvth, pvtl, nullptr, penc, nullptr, nullptr, DD, NKV,
        (long)TT*NKV, (long)DD*NKV, (long)TT*DD, 1.f);
    // 10. pool + output
    pool_out_kernel<<<BB, 256>>>(labels, emb, w_out, b_out, out);
}

// round 7
// speedup vs baseline: 3.6207x; 1.9278x over previous
#include <cuda_runtime.h>
#include <cuda_bf16.h>
#include <cstdint>
#include <math.h>

#define BB 64
#define TT 512
#define NKV 512
#define DD 256
#define MTOT (BB*TT)
#define EPSLN 1e-5f

// ======================= scratch (device globals) ===========================
__device__ __align__(256) __nv_bfloat16 g_xb[MTOT*DD];
__device__ __align__(256) __nv_bfloat16 g_hb[MTOT*DD];
__device__ __align__(256) __nv_bfloat16 g_wqt[DD*DD];
__device__ __align__(256) __nv_bfloat16 g_wkt[DD*DD];
__device__ __align__(256) __nv_bfloat16 g_wvt[DD*DD];
__device__ __align__(256) __nv_bfloat16 g_qb[MTOT*DD];
__device__ __align__(256) __nv_bfloat16 g_kb[MTOT*DD];
__device__ __align__(256) __nv_bfloat16 g_vt[BB*DD*NKV];
__device__ __align__(256) __nv_bfloat16 g_ab[BB*TT*NKV];
__device__ __align__(256) float g_sc[BB*TT*NKV];
__device__ __align__(256) float g_enc[MTOT*DD];

// ======================= PTX helpers (baseline ISA only) ====================
__device__ __forceinline__ uint32_t smem_to_u32(const void* p) {
    uint32_t a;
    asm("{ .reg .u64 t; cvta.to.shared.u64 t, %1; cvt.u32.u64 %0, t; }" : "=r"(a) : "l"(p));
    return a;
}
#define CP_ASYNC16(dst_u32, src_ptr) \
    asm volatile("cp.async.cg.shared.global [%0], [%1], 16;" \
        :: "r"(dst_u32), "l"(src_ptr))
#define CP_ASYNC_COMMIT() asm volatile("cp.async.commit_group;" ::: "memory")
#define CP_ASYNC_WAIT0()  asm volatile("cp.async.wait_group 0;" ::: "memory")
#define CP_ASYNC_WAIT1()  asm volatile("cp.async.wait_group 1;" ::: "memory")

__device__ __forceinline__ void ldsm4(uint32_t* r, uint32_t addr) {
    asm volatile("ldmatrix.sync.aligned.m8n8.x4.shared.b16 {%0,%1,%2,%3}, [%4];"
        : "=r"(r[0]), "=r"(r[1]), "=r"(r[2]), "=r"(r[3]) : "r"(addr));
}
// D(f32) += A(bf16 m16k16 row) * B(bf16 k16n8 col)
__device__ __forceinline__ void mma_bf16(float* c, const uint32_t* a, const uint32_t* b) {
    asm volatile(
        "mma.sync.aligned.m16n8k16.row.col.f32.bf16.bf16.f32 "
        "{%0,%1,%2,%3}, {%4,%5,%6,%7}, {%8,%9}, {%0,%1,%2,%3};"
        : "+f"(c[0]), "+f"(c[1]), "+f"(c[2]), "+f"(c[3])
        : "r"(a[0]), "r"(a[1]), "r"(a[2]), "r"(a[3]), "r"(b[0]), "r"(b[1]));
}

// ======================= reductions =========================================
__device__ __forceinline__ float warp_sum(float v) {
    #pragma unroll
    for (int o = 16; o > 0; o >>= 1) v += __shfl_xor_sync(0xffffffffu, v, o);
    return v;
}
__device__ __forceinline__ float warp_max(float v) {
    #pragma unroll
    for (int o = 16; o > 0; o >>= 1) v = fmaxf(v, __shfl_xor_sync(0xffffffffu, v, o));
    return v;
}
__device__ __forceinline__ float block_sum(float v, float* red) {
    int lane = threadIdx.x & 31, wid = threadIdx.x >> 5;
    v = warp_sum(v);
    if (lane == 0) red[wid] = v;
    __syncthreads();
    v = (threadIdx.x < (blockDim.x >> 5)) ? red[threadIdx.x] : 0.f;
    if (wid == 0) v = warp_sum(v);
    if (threadIdx.x == 0) red[0] = v;
    __syncthreads();
    v = red[0];
    __syncthreads();
    return v;
}
__device__ __forceinline__ float block_max(float v, float* red) {
    int lane = threadIdx.x & 31, wid = threadIdx.x >> 5;
    v = warp_max(v);
    if (lane == 0) red[wid] = v;
    __syncthreads();
    v = (threadIdx.x < (blockDim.x >> 5)) ? red[threadIdx.x] : -3.4e38f;
    if (wid == 0) v = warp_max(v);
    if (threadIdx.x == 0) red[0] = v;
    __syncthreads();
    v = red[0];
    __syncthreads();
    return v;
}

// ======================= elementwise kernels ================================
__global__ __launch_bounds__(256) void build_x_kernel(
    const float* __restrict__ traj, const int* __restrict__ labels,
    const float* __restrict__ w_mlp, const float* __restrict__ b_mlp,
    const float* __restrict__ ln_g, const float* __restrict__ ln_b,
    const float* __restrict__ emb)
{
    int row = blockIdx.x;
    int b   = row >> 9;
    int d   = threadIdx.x;
    float t0 = traj[row*2 + 0];
    float t1 = traj[row*2 + 1];
    float v  = t0 * w_mlp[d] + t1 * w_mlp[DD + d] + b_mlp[d];

    __shared__ float red[32];
    float mean = block_sum(v, red) * (1.f/DD);
    float dv   = v - mean;
    float var  = block_sum(dv*dv, red) * (1.f/DD);
    float y = dv * rsqrtf(var + EPSLN) * ln_g[d] + ln_b[d];
    y = (y > 0.f) ? y : 0.01f * y;
    float xv = y + emb[labels[b]*DD + d];
    g_xb[(long)row*DD + d] = __float2bfloat16(xv);
}

__global__ __launch_bounds__(256) void conv_bf16_kernel(
    const float* __restrict__ in, __nv_bfloat16* __restrict__ ob, int n4)
{
    int i = blockIdx.x*256 + threadIdx.x;
    if (i >= n4) return;
    float4 v = ((const float4*)in)[i];
    uint32_t w0 = (uint32_t)__bfloat16_as_ushort(__float2bfloat16(v.x))
                | ((uint32_t)__bfloat16_as_ushort(__float2bfloat16(v.y)) << 16);
    uint32_t w1 = (uint32_t)__bfloat16_as_ushort(__float2bfloat16(v.z))
                | ((uint32_t)__bfloat16_as_ushort(__float2bfloat16(v.w)) << 16);
    ((uint2*)ob)[i] = make_uint2(w0, w1);
}

// w[k][n] (256x256) -> wT[n][k]
__global__ __launch_bounds__(256) void convT_kernel(
    const float* __restrict__ w, __nv_bfloat16* __restrict__ ob)
{
    int n = blockIdx.x, k = threadIdx.x;
    ob[n*DD + k] = __float2bfloat16(w[k*DD + n]);
}

__global__ __launch_bounds__(256) void softmax_kernel(const int* __restrict__ valid_len)
{
    int row = blockIdx.x;
    int b   = row >> 9;
    const float* s = g_sc + (long)row * NKV;
    int vl = valid_len[b];
    int j0 = threadIdx.x, j1 = threadIdx.x + 256;
    float s0 = (j0 < vl) ? s[j0] : -1e9f;
    float s1 = (j1 < vl) ? s[j1] : -1e9f;

    __shared__ float red[32];
    float m   = block_max(fmaxf(s0, s1), red);
    float e0  = __expf(s0 - m);
    float e1  = __expf(s1 - m);
    float sum = block_sum(e0 + e1, red);
    float inv = 1.f / sum;
    g_ab[(long)row*NKV + j0] = __float2bfloat16(e0 * inv);
    g_ab[(long)row*NKV + j1] = __float2bfloat16(e1 * inv);
}

__global__ __launch_bounds__(256) void pool_out_kernel(
    const int* __restrict__ labels, const float* __restrict__ emb,
    const float* __restrict__ w_out, const float* __restrict__ b_out,
    float* __restrict__ out)
{
    int b = blockIdx.x;
    int d = threadIdx.x;
    const float* e = g_enc + (long)b*TT*DD + d;
    float m = -3.4e38f;
    #pragma unroll 8
    for (int t = 0; t < TT; t++) m = fmaxf(m, e[(long)t*DD]);
    float p = m + emb[labels[b]*DD + d];

    __shared__ float red[32];
    float sum = block_sum(p * w_out[d], red);
    if (threadIdx.x == 0)
        out[b] = 1.f / (1.f + __expf(-(sum + b_out[0])));
}

// ======================= mma.sync GEMM ======================================
// C = scale * A @ B^T (+ bias).  A: [M,K] K-major bf16; B: [Nglob,K] K-major bf16.
// MODE 0: Cf (fp32, *scale).  MODE 1: Cb bf16 + bias[n].  MODE 2: Cb bf16 + bias[m].
// Block tile 128(m) x 256(n), K-chunk 64, 8 warps (2m x 4n), warp tile 64x64.
// SMEM rows padded to 144B (64 bf16 + 8) -> conflict-mitigated ldmatrix.
#define LDSROW   144
#define A_SB     (128*LDSROW)        // 18432 B
#define B_SB     (256*LDSROW)        // 36864 B
#define STAGE    (A_SB + B_SB)       // 55296 B
#define SMEM_REQ (2*STAGE)           // 110592 B

template<int MODE>
__global__ __launch_bounds__(256, 1) void mma_gemm_kernel(
    const __nv_bfloat16* __restrict__ A, const __nv_bfloat16* __restrict__ B,
    const float* __restrict__ bias,
    float* __restrict__ Cf, __nv_bfloat16* __restrict__ Cb,
    int N, int K, long sA, long sB, long sC, float scale)
{
    extern __shared__ char dsm[];
    const uint32_t sm0 = smem_to_u32(dsm);

    const int tid  = threadIdx.x;
    const int lane = tid & 31;
    const int w    = tid >> 5;
    const int wm   = w & 1;          // m offset wm*64
    const int wn   = w >> 1;         // n offset wn*64

    A += (long)blockIdx.z * sA;
    B += (long)blockIdx.z * sB;
    const long czoff = (long)blockIdx.z * sC;
    const int m0 = blockIdx.y * 128;
    const int n0 = blockIdx.x * 256;

    float acc[4][8][4] = {};   // [mt][nt][c]

    // K-chunk = 64 bf16 = 128 B = 8 x 16B segments per row.
    // A: 128 rows * 8 segs = 1024 copies; B: 256 rows * 8 segs = 2048 copies.
    // Total 3072 = 12 iterations x 256 threads.
    auto prefetch = [&](int c) {
        const int kc = c << 6;
        const uint32_t sb = sm0 + (c & 1) * STAGE;
        #pragma unroll
        for (int t = 0; t < 12; t++) {
            int idx = t*256 + tid;               // 0..3071
            if (idx < 1024) {                    // A: 128 rows x 8 segs
                int row = idx >> 3, seg = idx & 7;
                CP_ASYNC16(sb + row*LDSROW + seg*16,
                           A + (long)(m0 + row)*K + kc + seg*8);
            } else {                             // B: 256 rows x 8 segs
                int j = idx - 1024;
                int row = j >> 3, seg = j & 7;
                CP_ASYNC16(sb + A_SB + row*LDSROW + seg*16,
                           B + (long)(n0 + row)*K + kc + seg*8);
            }
        }
        CP_ASYNC_COMMIT();
    };

    const int nch = K >> 6;
    prefetch(0);
    for (int c = 0; c < nch; c++) {
        if (c + 1 < nch) { prefetch(c + 1); CP_ASYNC_WAIT1(); }
        else             { CP_ASYNC_WAIT0(); }
        __syncthreads();

        const uint32_t sb = sm0 + (c & 1) * STAGE;
        #pragma unroll
        for (int ks = 0; ks < 4; ks++) {
            uint32_t aF[4][4], bF[8][2];
            // A fragments: m16k16; lane -> row (lane&15), k-col ((lane>>4)&1)*8
            {
                const int arow = wm*64 + (lane & 15);
                const int acol = (ks*16 + ((lane >> 4) & 1)*8) * 2;
                #pragma unroll
                for (int mt = 0; mt < 4; mt++)
                    ldsm4(aF[mt], sb + (arow + mt*16)*LDSROW + acol);
            }
            // B fragments: k16n16 per ldsm4 (two n8 frags)
            {
                const int bcol = (ks*16 + ((lane >> 3) & 1)*8) * 2;
                #pragma unroll
                for (int g = 0; g < 4; g++) {
                    const int brow = wn*64 + g*16 + ((lane >> 4) & 1)*8 + (lane & 7);
                    uint32_t t4[4];
                    ldsm4(t4, sb + A_SB + brow*LDSROW + bcol);
                    bF[2*g+0][0] = t4[0]; bF[2*g+0][1] = t4[1];
                    bF[2*g+1][0] = t4[2]; bF[2*g+1][1] = t4[3];
                }
            }
            #pragma unroll
            for (int mt = 0; mt < 4; mt++)
                #pragma unroll
                for (int nt = 0; nt < 8; nt++)
                    mma_bf16(acc[mt][nt], aF[mt], bF[nt]);
        }
        __syncthreads();
    }

    // ======================= epilogue =======================================
    #pragma unroll
    for (int mt = 0; mt < 4; mt++) {
        #pragma unroll
        for (int nt = 0; nt < 8; nt++) {
            int mg = m0 + wm*64 + mt*16 + (lane >> 2);
            int ng = n0 + wn*64 + nt*8 + (lane & 3)*2;
            float v0 = acc[mt][nt][0], v1 = acc[mt][nt][1];
            float v2 = acc[mt][nt][2], v3 = acc[mt][nt][3];
            if (MODE == 0) {
                *(float2*)&Cf[czoff + (long)mg*N + ng]     = make_float2(v0*scale, v1*scale);
                *(float2*)&Cf[czoff + (long)(mg+8)*N + ng] = make_float2(v2*scale, v3*scale);
            } else {
                if (MODE == 1) {
                    float b0 = bias[ng], b1 = bias[ng+1];
                    v0 += b0; v1 += b1; v2 += b0; v3 += b1;
                } else {
                    float b0 = bias[mg], b1 = bias[mg+8];
                    v0 += b0; v1 += b0; v2 += b1; v3 += b1;
                }
                uint32_t w0 = (uint32_t)__bfloat16_as_ushort(__float2bfloat16(v0))
                            | ((uint32_t)__bfloat16_as_ushort(__float2bfloat16(v1)) << 16);
                uint32_t w1 = (uint32_t)__bfloat16_as_ushort(__float2bfloat16(v2))
                            | ((uint32_t)__bfloat16_as_ushort(__float2bfloat16(v3)) << 16);
                *(uint32_t*)&Cb[czoff + (long)mg*N + ng]     = w0;
                *(uint32_t*)&Cb[czoff + (long)(mg+8)*N + ng] = w1;
            }
        }
    }
}

// ======================= launch =============================================
extern "C" void kernel_launch(void* const* d_in, const int* in_sizes, int n_in,
                              void* d_out, int out_size)
{
    const float* traj      = (const float*)d_in[0];
    const int*   labels    = (const int*)  d_in[1];
    const float* h         = (const float*)d_in[2];
    const int*   valid_len = (const int*)  d_in[3];
    const float* emb       = (const float*)d_in[4];
    const float* w_mlp     = (const float*)d_in[5];
    const float* b_mlp     = (const float*)d_in[6];
    const float* ln_g      = (const float*)d_in[7];
    const float* ln_b      = (const float*)d_in[8];
    const float* wq        = (const float*)d_in[9];
    const float* bq        = (const float*)d_in[10];
    const float* wk        = (const float*)d_in[11];
    const float* bk        = (const float*)d_in[12];
    const float* wv        = (const float*)d_in[13];
    const float* bv        = (const float*)d_in[14];
    const float* w_out     = (const float*)d_in[15];
    const float* b_out     = (const float*)d_in[16];
    float* out = (float*)d_out;

    cudaFuncSetAttribute(mma_gemm_kernel<0>, cudaFuncAttributeMaxDynamicSharedMemorySize, SMEM_REQ);
    cudaFuncSetAttribute(mma_gemm_kernel<1>, cudaFuncAttributeMaxDynamicSharedMemorySize, SMEM_REQ);
    cudaFuncSetAttribute(mma_gemm_kernel<2>, cudaFuncAttributeMaxDynamicSharedMemorySize, SMEM_REQ);

    __nv_bfloat16 *pxb, *phb, *pwqt, *pwkt, *pwvt, *pqb, *pkb, *pvt, *pab;
    float *psc, *penc;
    cudaGetSymbolAddress((void**)&pxb,  g_xb);
    cudaGetSymbolAddress((void**)&phb,  g_hb);
    cudaGetSymbolAddress((void**)&pwqt, g_wqt);
    cudaGetSymbolAddress((void**)&pwkt, g_wkt);
    cudaGetSymbolAddress((void**)&pwvt, g_wvt);
    cudaGetSymbolAddress((void**)&pqb,  g_qb);
    cudaGetSymbolAddress((void**)&pkb,  g_kb);
    cudaGetSymbolAddress((void**)&pvt,  g_vt);
    cudaGetSymbolAddress((void**)&pab,  g_ab);
    cudaGetSymbolAddress((void**)&psc,  g_sc);
    cudaGetSymbolAddress((void**)&penc, g_enc);

    // 1. x = leaky(LN(traj@w_mlp)) + le  -> bf16
    build_x_kernel<<<MTOT, 256>>>(traj, labels, w_mlp, b_mlp, ln_g, ln_b, emb);
    // 2. h -> bf16
    conv_bf16_kernel<<<(MTOT*DD/4 + 255)/256, 256>>>(h, phb, MTOT*DD/4);
    // 3. transposed weights -> bf16
    convT_kernel<<<DD, DD>>>(wq, pwqt);
    convT_kernel<<<DD, DD>>>(wk, pwkt);
    convT_kernel<<<DD, DD>>>(wv, pwvt);

    // 4. q = x@wq + bq  (bf16 out, col bias)   M=32768, N=256, K=256
    mma_gemm_kernel<1><<<dim3(1, 256, 1), 256, SMEM_REQ>>>(
        pxb, pwqt, bq, nullptr, pqb, DD, DD, 0, 0, 0, 1.f);
    // 5. k = h@wk + bk
    mma_gemm_kernel<1><<<dim3(1, 256, 1), 256, SMEM_REQ>>>(
        phb, pwkt, bk, nullptr, pkb, DD, DD, 0, 0, 0, 1.f);
    // 6. vT[b][d][n] = wvT @ h^T + bv[d]  (bf16 out, row bias)  M=256, N=512, K=256
    mma_gemm_kernel<2><<<dim3(2, 2, BB), 256, SMEM_REQ>>>(
        pwvt, phb, bv, nullptr, pvt, NKV, DD,
        0, (long)NKV*DD, (long)DD*NKV, 1.f);
    // 7. scores = q@k^T / 16  (fp32 out)  per-batch M=512, N=512, K=256
    mma_gemm_kernel<0><<<dim3(2, 4, BB), 256, SMEM_REQ>>>(
        pqb, pkb, nullptr, psc, nullptr, NKV, DD,
        (long)TT*DD, (long)NKV*DD, (long)TT*NKV, 0.0625f);
    // 8. masked softmax -> attn bf16
    softmax_kernel<<<BB*TT, 256>>>(valid_len);
    // 9. enc = attn@v  (fp32 out)  per-batch M=512, N=256, K=512
    mma_gemm_kernel<0><<<dim3(1, 4, BB), 256, SMEM_REQ>>>(
        pab, pvt, nullptr, penc, nullptr, DD, NKV,
        (long)TT*NKV, (long)DD*NKV, (long)TT*DD, 1.f);
    // 10. pool + output
    pool_out_kernel<<<BB, 256>>>(labels, emb, w_out, b_out, out);
}

// round 8
// speedup vs baseline: 4.6271x; 1.2780x over previous
#include <cuda_runtime.h>
#include <cuda_bf16.h>
#include <cstdint>
#include <math.h>

#define BB 64
#define TT 512
#define NKV 512
#define DD 256
#define MTOT (BB*TT)
#define EPSLN 1e-5f

// ======================= scratch (device globals) ===========================
__device__ __align__(256) __nv_bfloat16 g_xh2[2*MTOT*DD];   // [0]=x, [1]=h
__device__ __align__(256) __nv_bfloat16 g_wt2[2*DD*DD];     // [0]=wqT, [1]=wkT
__device__ __align__(256) __nv_bfloat16 g_wvt[DD*DD];
__device__ __align__(256) float         g_b2[2*DD];         // bq, bk
__device__ __align__(256) __nv_bfloat16 g_qk[2*MTOT*DD];    // [0]=q, [1]=k
__device__ __align__(256) __nv_bfloat16 g_vt[BB*DD*NKV];
__device__ __align__(256) __nv_bfloat16 g_ab[BB*TT*NKV];
__device__ __align__(256) float         g_sc[BB*TT*NKV];
__device__ __align__(256) unsigned      g_poolu[BB*DD];

// ======================= PTX helpers (baseline ISA only) ====================
__device__ __forceinline__ uint32_t smem_to_u32(const void* p) {
    uint32_t a;
    asm("{ .reg .u64 t; cvta.to.shared.u64 t, %1; cvt.u32.u64 %0, t; }" : "=r"(a) : "l"(p));
    return a;
}
#define CP_ASYNC16(dst_u32, src_ptr) \
    asm volatile("cp.async.cg.shared.global [%0], [%1], 16;" \
        :: "r"(dst_u32), "l"(src_ptr))
#define CP_ASYNC_COMMIT() asm volatile("cp.async.commit_group;" ::: "memory")
#define CP_ASYNC_WAIT0()  asm volatile("cp.async.wait_group 0;" ::: "memory")
#define CP_ASYNC_WAIT1()  asm volatile("cp.async.wait_group 1;" ::: "memory")

__device__ __forceinline__ void ldsm4(uint32_t* r, uint32_t addr) {
    asm volatile("ldmatrix.sync.aligned.m8n8.x4.shared.b16 {%0,%1,%2,%3}, [%4];"
        : "=r"(r[0]), "=r"(r[1]), "=r"(r[2]), "=r"(r[3]) : "r"(addr));
}
__device__ __forceinline__ void mma_bf16(float* c, const uint32_t* a, const uint32_t* b) {
    asm volatile(
        "mma.sync.aligned.m16n8k16.row.col.f32.bf16.bf16.f32 "
        "{%0,%1,%2,%3}, {%4,%5,%6,%7}, {%8,%9}, {%0,%1,%2,%3};"
        : "+f"(c[0]), "+f"(c[1]), "+f"(c[2]), "+f"(c[3])
        : "r"(a[0]), "r"(a[1]), "r"(a[2]), "r"(a[3]), "r"(b[0]), "r"(b[1]));
}

// order-preserving float<->unsigned for atomicMax
__device__ __forceinline__ unsigned encf(float f) {
    unsigned u = __float_as_uint(f);
    return (u & 0x80000000u) ? ~u : (u | 0x80000000u);
}
__device__ __forceinline__ float decf(unsigned u) {
    unsigned b = (u & 0x80000000u) ? (u ^ 0x80000000u) : ~u;
    return __uint_as_float(b);
}

// ======================= reductions =========================================
__device__ __forceinline__ float warp_sum(float v) {
    #pragma unroll
    for (int o = 16; o > 0; o >>= 1) v += __shfl_xor_sync(0xffffffffu, v, o);
    return v;
}
__device__ __forceinline__ float warp_max(float v) {
    #pragma unroll
    for (int o = 16; o > 0; o >>= 1) v = fmaxf(v, __shfl_xor_sync(0xffffffffu, v, o));
    return v;
}
__device__ __forceinline__ float block_sum(float v, float* red) {
    int lane = threadIdx.x & 31, wid = threadIdx.x >> 5;
    v = warp_sum(v);
    if (lane == 0) red[wid] = v;
    __syncthreads();
    v = (threadIdx.x < (blockDim.x >> 5)) ? red[threadIdx.x] : 0.f;
    if (wid == 0) v = warp_sum(v);
    if (threadIdx.x == 0) red[0] = v;
    __syncthreads();
    v = red[0];
    __syncthreads();
    return v;
}
__device__ __forceinline__ float block_max(float v, float* red) {
    int lane = threadIdx.x & 31, wid = threadIdx.x >> 5;
    v = warp_max(v);
    if (lane == 0) red[wid] = v;
    __syncthreads();
    v = (threadIdx.x < (blockDim.x >> 5)) ? red[threadIdx.x] : -3.4e38f;
    if (wid == 0) v = warp_max(v);
    if (threadIdx.x == 0) red[0] = v;
    __syncthreads();
    v = red[0];
    __syncthreads();
    return v;
}

// ======================= elementwise kernels ================================
__global__ __launch_bounds__(256) void build_x_kernel(
    const float* __restrict__ traj, const int* __restrict__ labels,
    const float* __restrict__ w_mlp, const float* __restrict__ b_mlp,
    const float* __restrict__ ln_g, const float* __restrict__ ln_b,
    const float* __restrict__ emb)
{
    int row = blockIdx.x;
    int b   = row >> 9;
    int d   = threadIdx.x;
    float t0 = traj[row*2 + 0];
    float t1 = traj[row*2 + 1];
    float v  = t0 * w_mlp[d] + t1 * w_mlp[DD + d] + b_mlp[d];

    __shared__ float red[32];
    float mean = block_sum(v, red) * (1.f/DD);
    float dv   = v - mean;
    float var  = block_sum(dv*dv, red) * (1.f/DD);
    float y = dv * rsqrtf(var + EPSLN) * ln_g[d] + ln_b[d];
    y = (y > 0.f) ? y : 0.01f * y;
    float xv = y + emb[labels[b]*DD + d];
    g_xh2[(long)row*DD + d] = __float2bfloat16(xv);
}

// h -> bf16 into g_xh2 slot 1; also zero-init pool buffer
__global__ __launch_bounds__(256) void conv_bf16_kernel(
    const float* __restrict__ in, int n4)
{
    int i = blockIdx.x*256 + threadIdx.x;
    if (i < BB*DD) g_poolu[i] = 0u;
    if (i >= n4) return;
    float4 v = ((const float4*)in)[i];
    uint32_t w0 = (uint32_t)__bfloat16_as_ushort(__float2bfloat16(v.x))
                | ((uint32_t)__bfloat16_as_ushort(__float2bfloat16(v.y)) << 16);
    uint32_t w1 = (uint32_t)__bfloat16_as_ushort(__float2bfloat16(v.z))
                | ((uint32_t)__bfloat16_as_ushort(__float2bfloat16(v.w)) << 16);
    ((uint2*)(g_xh2 + (long)MTOT*DD))[i] = make_uint2(w0, w1);
}

// wq,wk,wv [k][n] -> transposed bf16; pack bq,bk
__global__ __launch_bounds__(256) void convT_all_kernel(
    const float* __restrict__ wq, const float* __restrict__ wk,
    const float* __restrict__ wv,
    const float* __restrict__ bq, const float* __restrict__ bk)
{
    int w = blockIdx.x >> 8;     // 0..2
    int n = blockIdx.x & 255;
    int k = threadIdx.x;
    const float* src = (w == 0) ? wq : (w == 1) ? wk : wv;
    __nv_bfloat16* dst = (w == 0) ? g_wt2 : (w == 1) ? (g_wt2 + DD*DD) : g_wvt;
    dst[n*DD + k] = __float2bfloat16(src[k*DD + n]);
    if (blockIdx.x == 0) g_b2[k] = bq[k];
    if (blockIdx.x == 1) g_b2[DD + k] = bk[k];
}

__global__ __launch_bounds__(256) void softmax_kernel(const int* __restrict__ valid_len)
{
    int row = blockIdx.x;
    int b   = row >> 9;
    const float* s = g_sc + (long)row * NKV;
    int vl = valid_len[b];
    int j0 = threadIdx.x, j1 = threadIdx.x + 256;
    float s0 = (j0 < vl) ? s[j0] : -1e9f;
    float s1 = (j1 < vl) ? s[j1] : -1e9f;

    __shared__ float red[32];
    float m   = block_max(fmaxf(s0, s1), red);
    float e0  = __expf(s0 - m);
    float e1  = __expf(s1 - m);
    float sum = block_sum(e0 + e1, red);
    float inv = 1.f / sum;
    g_ab[(long)row*NKV + j0] = __float2bfloat16(e0 * inv);
    g_ab[(long)row*NKV + j1] = __float2bfloat16(e1 * inv);
}

__global__ __launch_bounds__(256) void pool_out_kernel(
    const int* __restrict__ labels, const float* __restrict__ emb,
    const float* __restrict__ w_out, const float* __restrict__ b_out,
    float* __restrict__ out)
{
    int b = blockIdx.x;
    int d = threadIdx.x;
    float m = decf(g_poolu[b*DD + d]);
    float p = m + emb[labels[b]*DD + d];

    __shared__ float red[32];
    float sum = block_sum(p * w_out[d], red);
    if (threadIdx.x == 0)
        out[b] = 1.f / (1.f + __expf(-(sum + b_out[0])));
}

// ======================= mma.sync GEMM ======================================
// C = scale * A @ B^T (+ bias).  A: [M,K] K-major bf16; B: [Nglob,K] K-major bf16.
// MODE 0: Cf fp32 *scale.  MODE 1: Cb bf16 + bias[z*sBias + n].
// MODE 2: Cb bf16 + bias[m].  MODE 3: no store; atomicMax pooled column max.
// VLM 0: none. 1: K-limit at ceil(vl[z]/64). 2: exit if n0 >= vl[z].
// VLM 3: exit if z==1 && (m0&511) >= vl[m0>>9]  (merged q/k projection).
#define LDSROW   144
#define A_SB     (128*LDSROW)
#define B_SB     (256*LDSROW)
#define STAGE    (A_SB + B_SB)
#define SMEM_REQ (2*STAGE)           // 110592 B

template<int MODE, int VLM>
__global__ __launch_bounds__(256, 1) void mma_gemm_kernel(
    const __nv_bfloat16* __restrict__ A, const __nv_bfloat16* __restrict__ B,
    const float* __restrict__ bias,
    float* __restrict__ Cf, __nv_bfloat16* __restrict__ Cb,
    unsigned* __restrict__ Pool, const int* __restrict__ vlen,
    int N, int K, long sA, long sB, long sC, long sBias, float scale)
{
    extern __shared__ char dsm[];
    const uint32_t sm0 = smem_to_u32(dsm);

    const int tid  = threadIdx.x;
    const int lane = tid & 31;
    const int w    = tid >> 5;
    const int wm   = w & 1;
    const int wn   = w >> 1;

    const int m0 = blockIdx.y * 128;
    const int n0 = blockIdx.x * 256;

    int nch_e = K >> 6;
    if (VLM == 1) { int vl = vlen[blockIdx.z]; nch_e = (vl + 63) >> 6; }
    if (VLM == 2) { if (n0 >= vlen[blockIdx.z]) return; }
    if (VLM == 3) { if (blockIdx.z == 1 && (m0 & 511) >= vlen[m0 >> 9]) return; }

    A += (long)blockIdx.z * sA;
    B += (long)blockIdx.z * sB;
    const long czoff = (long)blockIdx.z * sC;

    float acc[4][8][4] = {};

    auto prefetch = [&](int c) {
        const int kc = c << 6;
        const uint32_t sb = sm0 + (c & 1) * STAGE;
        #pragma unroll
        for (int t = 0; t < 12; t++) {
            int idx = t*256 + tid;
            if (idx < 1024) {
                int row = idx >> 3, seg = idx & 7;
                CP_ASYNC16(sb + row*LDSROW + seg*16,
                           A + (long)(m0 + row)*K + kc + seg*8);
            } else {
                int j = idx - 1024;
                int row = j >> 3, seg = j & 7;
                CP_ASYNC16(sb + A_SB + row*LDSROW + seg*16,
                           B + (long)(n0 + row)*K + kc + seg*8);
            }
        }
        CP_ASYNC_COMMIT();
    };

    prefetch(0);
    for (int c = 0; c < nch_e; c++) {
        if (c + 1 < nch_e) { prefetch(c + 1); CP_ASYNC_WAIT1(); }
        else               { CP_ASYNC_WAIT0(); }
        __syncthreads();

        const uint32_t sb = sm0 + (c & 1) * STAGE;
        #pragma unroll
        for (int ks = 0; ks < 4; ks++) {
            uint32_t aF[4][4], bF[8][2];
            {
                const int arow = wm*64 + (lane & 15);
                const int acol = (ks*16 + ((lane >> 4) & 1)*8) * 2;
                #pragma unroll
                for (int mt = 0; mt < 4; mt++)
                    ldsm4(aF[mt], sb + (arow + mt*16)*LDSROW + acol);
            }
            {
                const int bcol = (ks*16 + ((lane >> 3) & 1)*8) * 2;
                #pragma unroll
                for (int g = 0; g < 4; g++) {
                    const int brow = wn*64 + g*16 + ((lane >> 4) & 1)*8 + (lane & 7);
                    uint32_t t4[4];
                    ldsm4(t4, sb + A_SB + brow*LDSROW + bcol);
                    bF[2*g+0][0] = t4[0]; bF[2*g+0][1] = t4[1];
                    bF[2*g+1][0] = t4[2]; bF[2*g+1][1] = t4[3];
                }
            }
            #pragma unroll
            for (int mt = 0; mt < 4; mt++)
                #pragma unroll
                for (int nt = 0; nt < 8; nt++)
                    mma_bf16(acc[mt][nt], aF[mt], bF[nt]);
        }
        __syncthreads();
    }

    // ======================= epilogue =======================================
    if (MODE == 3) {
        // pooled column max over this CTA's 128 m-rows, atomic into Pool[z][n]
        #pragma unroll
        for (int nt = 0; nt < 8; nt++) {
            int ng = n0 + wn*64 + nt*8 + (lane & 3)*2;
            float c0 = -3.4e38f, c1 = -3.4e38f;
            #pragma unroll
            for (int mt = 0; mt < 4; mt++) {
                c0 = fmaxf(c0, fmaxf(acc[mt][nt][0], acc[mt][nt][2]));
                c1 = fmaxf(c1, fmaxf(acc[mt][nt][1], acc[mt][nt][3]));
            }
            #pragma unroll
            for (int o = 4; o < 32; o <<= 1) {
                c0 = fmaxf(c0, __shfl_xor_sync(0xffffffffu, c0, o));
                c1 = fmaxf(c1, __shfl_xor_sync(0xffffffffu, c1, o));
            }
            if ((lane >> 2) == 0) {
                atomicMax(&Pool[blockIdx.z*DD + ng],     encf(c0));
                atomicMax(&Pool[blockIdx.z*DD + ng + 1], encf(c1));
            }
        }
        return;
    }
    #pragma unroll
    for (int mt = 0; mt < 4; mt++) {
        #pragma unroll
        for (int nt = 0; nt < 8; nt++) {
            int mg = m0 + wm*64 + mt*16 + (lane >> 2);
            int ng = n0 + wn*64 + nt*8 + (lane & 3)*2;
            float v0 = acc[mt][nt][0], v1 = acc[mt][nt][1];
            float v2 = acc[mt][nt][2], v3 = acc[mt][nt][3];
            if (MODE == 0) {
                *(float2*)&Cf[czoff + (long)mg*N + ng]     = make_float2(v0*scale, v1*scale);
                *(float2*)&Cf[czoff + (long)(mg+8)*N + ng] = make_float2(v2*scale, v3*scale);
            } else {
                if (MODE == 1) {
                    float b0 = bias[blockIdx.z*sBias + ng], b1 = bias[blockIdx.z*sBias + ng + 1];
                    v0 += b0; v1 += b1; v2 += b0; v3 += b1;
                } else {
                    float b0 = bias[mg], b1 = bias[mg+8];
                    v0 += b0; v1 += b0; v2 += b1; v3 += b1;
                }
                uint32_t w0 = (uint32_t)__bfloat16_as_ushort(__float2bfloat16(v0))
                            | ((uint32_t)__bfloat16_as_ushort(__float2bfloat16(v1)) << 16);
                uint32_t w1 = (uint32_t)__bfloat16_as_ushort(__float2bfloat16(v2))
                            | ((uint32_t)__bfloat16_as_ushort(__float2bfloat16(v3)) << 16);
                *(uint32_t*)&Cb[czoff + (long)mg*N + ng]     = w0;
                *(uint32_t*)&Cb[czoff + (long)(mg+8)*N + ng] = w1;
            }
        }
    }
}

// ======================= launch =============================================
extern "C" void kernel_launch(void* const* d_in, const int* in_sizes, int n_in,
                              void* d_out, int out_size)
{
    const float* traj      = (const float*)d_in[0];
    const int*   labels    = (const int*)  d_in[1];
    const float* h         = (const float*)d_in[2];
    const int*   valid_len = (const int*)  d_in[3];
    const float* emb       = (const float*)d_in[4];
    const float* w_mlp     = (const float*)d_in[5];
    const float* b_mlp     = (const float*)d_in[6];
    const float* ln_g      = (const float*)d_in[7];
    const float* ln_b      = (const float*)d_in[8];
    const float* wq        = (const float*)d_in[9];
    const float* wk        = (const float*)d_in[11];
    const float* wv        = (const float*)d_in[13];
    const float* bq        = (const float*)d_in[10];
    const float* bk        = (const float*)d_in[12];
    const float* bv        = (const float*)d_in[14];
    const float* w_out     = (const float*)d_in[15];
    const float* b_out     = (const float*)d_in[16];
    float* out = (float*)d_out;

    cudaFuncSetAttribute(mma_gemm_kernel<0,2>, cudaFuncAttributeMaxDynamicSharedMemorySize, SMEM_REQ);
    cudaFuncSetAttribute(mma_gemm_kernel<1,3>, cudaFuncAttributeMaxDynamicSharedMemorySize, SMEM_REQ);
    cudaFuncSetAttribute(mma_gemm_kernel<2,2>, cudaFuncAttributeMaxDynamicSharedMemorySize, SMEM_REQ);
    cudaFuncSetAttribute(mma_gemm_kernel<3,1>, cudaFuncAttributeMaxDynamicSharedMemorySize, SMEM_REQ);

    __nv_bfloat16 *pxh2, *pwt2, *pwvt, *pqk, *pvt, *pab;
    float *pb2, *psc;
    unsigned *ppool;
    cudaGetSymbolAddress((void**)&pxh2,  g_xh2);
    cudaGetSymbolAddress((void**)&pwt2,  g_wt2);
    cudaGetSymbolAddress((void**)&pwvt,  g_wvt);
    cudaGetSymbolAddress((void**)&pb2,   g_b2);
    cudaGetSymbolAddress((void**)&pqk,   g_qk);
    cudaGetSymbolAddress((void**)&pvt,   g_vt);
    cudaGetSymbolAddress((void**)&pab,   g_ab);
    cudaGetSymbolAddress((void**)&psc,   g_sc);
    cudaGetSymbolAddress((void**)&ppool, g_poolu);

    __nv_bfloat16* pq = pqk;
    __nv_bfloat16* pk = pqk + (long)MTOT*DD;

    // 1. x = leaky(LN(traj@w_mlp)) + le -> bf16 (slot 0)
    build_x_kernel<<<MTOT, 256>>>(traj, labels, w_mlp, b_mlp, ln_g, ln_b, emb);
    // 2. h -> bf16 (slot 1) + pool init
    conv_bf16_kernel<<<(MTOT*DD/4 + 255)/256, 256>>>(h, MTOT*DD/4);
    // 3. transposed weights + packed biases
    convT_all_kernel<<<3*DD, DD>>>(wq, wk, wv, bq, bk);

    // 4. q,k = [x;h] @ [wq;wk] + [bq;bk]  (z=2 batched; skip k-rows >= vl)
    mma_gemm_kernel<1,3><<<dim3(1, 256, 2), 256, SMEM_REQ>>>(
        pxh2, pwt2, pb2, nullptr, pqk, nullptr, valid_len,
        DD, DD, (long)MTOT*DD, (long)DD*DD, (long)MTOT*DD, DD, 1.f);
    // 5. vT[b][d][n] = wvT @ h^T + bv[d]  (skip n-tiles >= vl)
    mma_gemm_kernel<2,2><<<dim3(2, 2, BB), 256, SMEM_REQ>>>(
        pwvt, pxh2 + (long)MTOT*DD, bv, nullptr, pvt, nullptr, valid_len,
        NKV, DD, 0, (long)NKV*DD, (long)DD*NKV, 0, 1.f);
    // 6. scores = q@k^T / 16  (skip n-tiles >= vl)
    mma_gemm_kernel<0,2><<<dim3(2, 4, BB), 256, SMEM_REQ>>>(
        pq, pk, nullptr, psc, nullptr, nullptr, valid_len,
        NKV, DD, (long)TT*DD, (long)NKV*DD, (long)TT*NKV, 0, 0.0625f);
    // 7. masked softmax -> attn bf16
    softmax_kernel<<<BB*TT, 256>>>(valid_len);
    // 8. enc = attn@v, fused max-pool via atomicMax (K-loop limited to ceil(vl/64))
    mma_gemm_kernel<3,1><<<dim3(1, 4, BB), 256, SMEM_REQ>>>(
        pab, pvt, nullptr, nullptr, nullptr, ppool, valid_len,
        DD, NKV, (long)TT*NKV, (long)DD*NKV, 0, 0, 1.f);
    // 9. output = sigmoid((pooled + le) @ w_out + b_out)
    pool_out_kernel<<<BB, 256>>>(labels, emb, w_out, b_out, out);
}

// round 9
// speedup vs baseline: 5.3736x; 1.1613x over previous
#include <cuda_runtime.h>
#include <cuda_bf16.h>
#include <cstdint>
#include <math.h>

#define BB 64
#define TT 512
#define NKV 512
#define DD 256
#define MTOT (BB*TT)
#define EPSLN 1e-5f

// ======================= scratch (device globals) ===========================
__device__ __align__(256) __nv_bfloat16 g_xh2[2*MTOT*DD];   // [0]=x, [1]=h
__device__ __align__(256) __nv_bfloat16 g_wt2[2*DD*DD];     // [0]=wqT, [1]=wkT
__device__ __align__(256) __nv_bfloat16 g_wvt[DD*DD];
__device__ __align__(256) float         g_b2[2*DD];         // bq, bk
__device__ __align__(256) __nv_bfloat16 g_qk[2*MTOT*DD];    // [0]=q, [1]=k
__device__ __align__(256) __nv_bfloat16 g_vt[BB*DD*NKV];
__device__ __align__(256) __nv_bfloat16 g_ab[BB*TT*NKV];
__device__ __align__(256) float         g_sc[BB*TT*NKV];
__device__ __align__(256) unsigned      g_poolu[BB*DD];

// ======================= PTX helpers (baseline ISA only) ====================
__device__ __forceinline__ uint32_t smem_to_u32(const void* p) {
    uint32_t a;
    asm("{ .reg .u64 t; cvta.to.shared.u64 t, %1; cvt.u32.u64 %0, t; }" : "=r"(a) : "l"(p));
    return a;
}
#define CP_ASYNC16(dst_u32, src_ptr) \
    asm volatile("cp.async.cg.shared.global [%0], [%1], 16;" \
        :: "r"(dst_u32), "l"(src_ptr))
#define CP_ASYNC_COMMIT() asm volatile("cp.async.commit_group;" ::: "memory")
#define CP_ASYNC_WAIT0()  asm volatile("cp.async.wait_group 0;" ::: "memory")
#define CP_ASYNC_WAIT1()  asm volatile("cp.async.wait_group 1;" ::: "memory")

__device__ __forceinline__ void ldsm4(uint32_t* r, uint32_t addr) {
    asm volatile("ldmatrix.sync.aligned.m8n8.x4.shared.b16 {%0,%1,%2,%3}, [%4];"
        : "=r"(r[0]), "=r"(r[1]), "=r"(r[2]), "=r"(r[3]) : "r"(addr));
}
__device__ __forceinline__ void mma_bf16(float* c, const uint32_t* a, const uint32_t* b) {
    asm volatile(
        "mma.sync.aligned.m16n8k16.row.col.f32.bf16.bf16.f32 "
        "{%0,%1,%2,%3}, {%4,%5,%6,%7}, {%8,%9}, {%0,%1,%2,%3};"
        : "+f"(c[0]), "+f"(c[1]), "+f"(c[2]), "+f"(c[3])
        : "r"(a[0]), "r"(a[1]), "r"(a[2]), "r"(a[3]), "r"(b[0]), "r"(b[1]));
}

// order-preserving float<->unsigned for atomicMax
__device__ __forceinline__ unsigned encf(float f) {
    unsigned u = __float_as_uint(f);
    return (u & 0x80000000u) ? ~u : (u | 0x80000000u);
}
__device__ __forceinline__ float decf(unsigned u) {
    unsigned b = (u & 0x80000000u) ? (u ^ 0x80000000u) : ~u;
    return __uint_as_float(b);
}

// ======================= reductions =========================================
__device__ __forceinline__ float warp_sum(float v) {
    #pragma unroll
    for (int o = 16; o > 0; o >>= 1) v += __shfl_xor_sync(0xffffffffu, v, o);
    return v;
}
__device__ __forceinline__ float warp_max(float v) {
    #pragma unroll
    for (int o = 16; o > 0; o >>= 1) v = fmaxf(v, __shfl_xor_sync(0xffffffffu, v, o));
    return v;
}
__device__ __forceinline__ float block_sum(float v, float* red) {
    int lane = threadIdx.x & 31, wid = threadIdx.x >> 5;
    v = warp_sum(v);
    if (lane == 0) red[wid] = v;
    __syncthreads();
    v = (threadIdx.x < (blockDim.x >> 5)) ? red[threadIdx.x] : 0.f;
    if (wid == 0) v = warp_sum(v);
    if (threadIdx.x == 0) red[0] = v;
    __syncthreads();
    v = red[0];
    __syncthreads();
    return v;
}
__device__ __forceinline__ float block_max(float v, float* red) {
    int lane = threadIdx.x & 31, wid = threadIdx.x >> 5;
    v = warp_max(v);
    if (lane == 0) red[wid] = v;
    __syncthreads();
    v = (threadIdx.x < (blockDim.x >> 5)) ? red[threadIdx.x] : -3.4e38f;
    if (wid == 0) v = warp_max(v);
    if (threadIdx.x == 0) red[0] = v;
    __syncthreads();
    v = red[0];
    __syncthreads();
    return v;
}

// ======================= elementwise kernels ================================
__global__ __launch_bounds__(256) void build_x_kernel(
    const float* __restrict__ traj, const int* __restrict__ labels,
    const float* __restrict__ w_mlp, const float* __restrict__ b_mlp,
    const float* __restrict__ ln_g, const float* __restrict__ ln_b,
    const float* __restrict__ emb)
{
    int row = blockIdx.x;
    int b   = row >> 9;
    int d   = threadIdx.x;
    float t0 = traj[row*2 + 0];
    float t1 = traj[row*2 + 1];
    float v  = t0 * w_mlp[d] + t1 * w_mlp[DD + d] + b_mlp[d];

    __shared__ float red[32];
    float mean = block_sum(v, red) * (1.f/DD);
    float dv   = v - mean;
    float var  = block_sum(dv*dv, red) * (1.f/DD);
    float y = dv * rsqrtf(var + EPSLN) * ln_g[d] + ln_b[d];
    y = (y > 0.f) ? y : 0.01f * y;
    float xv = y + emb[labels[b]*DD + d];
    g_xh2[(long)row*DD + d] = __float2bfloat16(xv);
}

// h -> bf16 into g_xh2 slot 1; also zero-init pool buffer
__global__ __launch_bounds__(256) void conv_bf16_kernel(
    const float* __restrict__ in, int n4)
{
    int i = blockIdx.x*256 + threadIdx.x;
    if (i < BB*DD) g_poolu[i] = 0u;
    if (i >= n4) return;
    float4 v = ((const float4*)in)[i];
    uint32_t w0 = (uint32_t)__bfloat16_as_ushort(__float2bfloat16(v.x))
                | ((uint32_t)__bfloat16_as_ushort(__float2bfloat16(v.y)) << 16);
    uint32_t w1 = (uint32_t)__bfloat16_as_ushort(__float2bfloat16(v.z))
                | ((uint32_t)__bfloat16_as_ushort(__float2bfloat16(v.w)) << 16);
    ((uint2*)(g_xh2 + (long)MTOT*DD))[i] = make_uint2(w0, w1);
}

// wq,wk,wv [k][n] -> transposed bf16; pack bq,bk
__global__ __launch_bounds__(256) void convT_all_kernel(
    const float* __restrict__ wq, const float* __restrict__ wk,
    const float* __restrict__ wv,
    const float* __restrict__ bq, const float* __restrict__ bk)
{
    int w = blockIdx.x >> 8;     // 0..2
    int n = blockIdx.x & 255;
    int k = threadIdx.x;
    const float* src = (w == 0) ? wq : (w == 1) ? wk : wv;
    __nv_bfloat16* dst = (w == 0) ? g_wt2 : (w == 1) ? (g_wt2 + DD*DD) : g_wvt;
    dst[n*DD + k] = __float2bfloat16(src[k*DD + n]);
    if (blockIdx.x == 0) g_b2[k] = bq[k];
    if (blockIdx.x == 1) g_b2[DD + k] = bk[k];
}

__global__ __launch_bounds__(256) void softmax_kernel(const int* __restrict__ valid_len)
{
    int row = blockIdx.x;
    int b   = row >> 9;
    const float* s = g_sc + (long)row * NKV;
    int vl = valid_len[b];
    int j0 = threadIdx.x, j1 = threadIdx.x + 256;
    float s0 = (j0 < vl) ? s[j0] : -1e9f;
    float s1 = (j1 < vl) ? s[j1] : -1e9f;

    __shared__ float red[32];
    float m   = block_max(fmaxf(s0, s1), red);
    float e0  = __expf(s0 - m);
    float e1  = __expf(s1 - m);
    float sum = block_sum(e0 + e1, red);
    float inv = 1.f / sum;
    g_ab[(long)row*NKV + j0] = __float2bfloat16(e0 * inv);
    g_ab[(long)row*NKV + j1] = __float2bfloat16(e1 * inv);
}

__global__ __launch_bounds__(256) void pool_out_kernel(
    const int* __restrict__ labels, const float* __restrict__ emb,
    const float* __restrict__ w_out, const float* __restrict__ b_out,
    float* __restrict__ out)
{
    int b = blockIdx.x;
    int d = threadIdx.x;
    float m = decf(g_poolu[b*DD + d]);
    float p = m + emb[labels[b]*DD + d];

    __shared__ float red[32];
    float sum = block_sum(p * w_out[d], red);
    if (threadIdx.x == 0)
        out[b] = 1.f / (1.f + __expf(-(sum + b_out[0])));
}

// ======================= mma.sync GEMM ======================================
// C = scale * A @ B^T (+ bias).  A: [M,K] K-major bf16; B: [Nglob,K] K-major bf16.
// MODE 0: Cf fp32 *scale.  MODE 1: Cb bf16 + bias[z*sBias + n].
// MODE 2: Cb bf16 + bias[m].  MODE 3: no store; atomicMax pooled column max.
// VLM 0: none. 1: K-limit at ceil(vl[z]/64). 2: exit if n0 >= vl[z].
// VLM 3: exit if z==1 && (m0&511) >= vl[m0>>9]  (merged q/k projection).
// Block tile 128(m) x 128(n), K-chunk 64, 8 warps (4m x 2n), warp tile 32x64.
// 2 CTAs/SM target: regs capped by __launch_bounds__(256,2), smem 72KB/CTA.
#define LDSROW   144
#define A_SB     (128*LDSROW)        // 18432 B
#define B_SB     (128*LDSROW)        // 18432 B
#define STAGE    (A_SB + B_SB)       // 36864 B
#define SMEM_REQ (2*STAGE)           // 73728 B

template<int MODE, int VLM>
__global__ __launch_bounds__(256, 2) void mma_gemm_kernel(
    const __nv_bfloat16* __restrict__ A, const __nv_bfloat16* __restrict__ B,
    const float* __restrict__ bias,
    float* __restrict__ Cf, __nv_bfloat16* __restrict__ Cb,
    unsigned* __restrict__ Pool, const int* __restrict__ vlen,
    int N, int K, long sA, long sB, long sC, long sBias, float scale)
{
    extern __shared__ char dsm[];
    const uint32_t sm0 = smem_to_u32(dsm);

    const int tid  = threadIdx.x;
    const int lane = tid & 31;
    const int w    = tid >> 5;
    const int wm   = w & 3;          // m offset wm*32
    const int wn   = w >> 2;         // n offset wn*64

    const int m0 = blockIdx.y * 128;
    const int n0 = blockIdx.x * 128;

    int nch_e = K >> 6;
    if (VLM == 1) { int vl = vlen[blockIdx.z]; nch_e = (vl + 63) >> 6; }
    if (VLM == 2) { if (n0 >= vlen[blockIdx.z]) return; }
    if (VLM == 3) { if (blockIdx.z == 1 && (m0 & 511) >= vlen[m0 >> 9]) return; }

    A += (long)blockIdx.z * sA;
    B += (long)blockIdx.z * sB;
    const long czoff = (long)blockIdx.z * sC;

    float acc[2][8][4] = {};   // [mt][nt][c]

    // K-chunk 64 bf16 = 8 x 16B segs/row. A:128x8=1024, B:128x8=1024 -> 8 iters.
    auto prefetch = [&](int c) {
        const int kc = c << 6;
        const uint32_t sb = sm0 + (c & 1) * STAGE;
        #pragma unroll
        for (int t = 0; t < 8; t++) {
            int idx = t*256 + tid;               // 0..2047
            int row = (idx >> 3) & 127, seg = idx & 7;
            if (idx < 1024) {
                CP_ASYNC16(sb + row*LDSROW + seg*16,
                           A + (long)(m0 + row)*K + kc + seg*8);
            } else {
                CP_ASYNC16(sb + A_SB + row*LDSROW + seg*16,
                           B + (long)(n0 + row)*K + kc + seg*8);
            }
        }
        CP_ASYNC_COMMIT();
    };

    prefetch(0);
    for (int c = 0; c < nch_e; c++) {
        if (c + 1 < nch_e) { prefetch(c + 1); CP_ASYNC_WAIT1(); }
        else               { CP_ASYNC_WAIT0(); }
        __syncthreads();

        const uint32_t sb = sm0 + (c & 1) * STAGE;
        #pragma unroll
        for (int ks = 0; ks < 4; ks++) {
            uint32_t aF[2][4], bF[8][2];
            {
                const int arow = wm*32 + (lane & 15);
                const int acol = (ks*16 + ((lane >> 4) & 1)*8) * 2;
                #pragma unroll
                for (int mt = 0; mt < 2; mt++)
                    ldsm4(aF[mt], sb + (arow + mt*16)*LDSROW + acol);
            }
            {
                const int bcol = (ks*16 + ((lane >> 3) & 1)*8) * 2;
                #pragma unroll
                for (int g = 0; g < 4; g++) {
                    const int brow = wn*64 + g*16 + ((lane >> 4) & 1)*8 + (lane & 7);
                    uint32_t t4[4];
                    ldsm4(t4, sb + A_SB + brow*LDSROW + bcol);
                    bF[2*g+0][0] = t4[0]; bF[2*g+0][1] = t4[1];
                    bF[2*g+1][0] = t4[2]; bF[2*g+1][1] = t4[3];
                }
            }
            #pragma unroll
            for (int mt = 0; mt < 2; mt++)
                #pragma unroll
                for (int nt = 0; nt < 8; nt++)
                    mma_bf16(acc[mt][nt], aF[mt], bF[nt]);
        }
        __syncthreads();
    }

    // ======================= epilogue =======================================
    if (MODE == 3) {
        // pooled column max over this CTA's 128 m-rows, atomic into Pool[z][n]
        #pragma unroll
        for (int nt = 0; nt < 8; nt++) {
            int ng = n0 + wn*64 + nt*8 + (lane & 3)*2;
            float c0 = -3.4e38f, c1 = -3.4e38f;
            #pragma unroll
            for (int mt = 0; mt < 2; mt++) {
                c0 = fmaxf(c0, fmaxf(acc[mt][nt][0], acc[mt][nt][2]));
                c1 = fmaxf(c1, fmaxf(acc[mt][nt][1], acc[mt][nt][3]));
            }
            #pragma unroll
            for (int o = 4; o < 32; o <<= 1) {
                c0 = fmaxf(c0, __shfl_xor_sync(0xffffffffu, c0, o));
                c1 = fmaxf(c1, __shfl_xor_sync(0xffffffffu, c1, o));
            }
            if ((lane >> 2) == 0) {
                atomicMax(&Pool[blockIdx.z*DD + ng],     encf(c0));
                atomicMax(&Pool[blockIdx.z*DD + ng + 1], encf(c1));
            }
        }
        return;
    }
    #pragma unroll
    for (int mt = 0; mt < 2; mt++) {
        #pragma unroll
        for (int nt = 0; nt < 8; nt++) {
            int mg = m0 + wm*32 + mt*16 + (lane >> 2);
            int ng = n0 + wn*64 + nt*8 + (lane & 3)*2;
            float v0 = acc[mt][nt][0], v1 = acc[mt][nt][1];
            float v2 = acc[mt][nt][2], v3 = acc[mt][nt][3];
            if (MODE == 0) {
                *(float2*)&Cf[czoff + (long)mg*N + ng]     = make_float2(v0*scale, v1*scale);
                *(float2*)&Cf[czoff + (long)(mg+8)*N + ng] = make_float2(v2*scale, v3*scale);
            } else {
                if (MODE == 1) {
                    float b0 = bias[blockIdx.z*sBias + ng], b1 = bias[blockIdx.z*sBias + ng + 1];
                    v0 += b0; v1 += b1; v2 += b0; v3 += b1;
                } else {
                    float b0 = bias[mg], b1 = bias[mg+8];
                    v0 += b0; v1 += b0; v2 += b1; v3 += b1;
                }
                uint32_t w0 = (uint32_t)__bfloat16_as_ushort(__float2bfloat16(v0))
                            | ((uint32_t)__bfloat16_as_ushort(__float2bfloat16(v1)) << 16);
                uint32_t w1 = (uint32_t)__bfloat16_as_ushort(__float2bfloat16(v2))
                            | ((uint32_t)__bfloat16_as_ushort(__float2bfloat16(v3)) << 16);
                *(uint32_t*)&Cb[czoff + (long)mg*N + ng]     = w0;
                *(uint32_t*)&Cb[czoff + (long)(mg+8)*N + ng] = w1;
            }
        }
    }
}

// ======================= launch =============================================
extern "C" void kernel_launch(void* const* d_in, const int* in_sizes, int n_in,
                              void* d_out, int out_size)
{
    const float* traj      = (const float*)d_in[0];
    const int*   labels    = (const int*)  d_in[1];
    const float* h         = (const float*)d_in[2];
    const int*   valid_len = (const int*)  d_in[3];
    const float* emb       = (const float*)d_in[4];
    const float* w_mlp     = (const float*)d_in[5];
    const float* b_mlp     = (const float*)d_in[6];
    const float* ln_g      = (const float*)d_in[7];
    const float* ln_b      = (const float*)d_in[8];
    const float* wq        = (const float*)d_in[9];
    const float* wk        = (const float*)d_in[11];
    const float* wv        = (const float*)d_in[13];
    const float* bq        = (const float*)d_in[10];
    const float* bk        = (const float*)d_in[12];
    const float* bv        = (const float*)d_in[14];
    const float* w_out     = (const float*)d_in[15];
    const float* b_out     = (const float*)d_in[16];
    float* out = (float*)d_out;

    cudaFuncSetAttribute(mma_gemm_kernel<0,2>, cudaFuncAttributeMaxDynamicSharedMemorySize, SMEM_REQ);
    cudaFuncSetAttribute(mma_gemm_kernel<1,3>, cudaFuncAttributeMaxDynamicSharedMemorySize, SMEM_REQ);
    cudaFuncSetAttribute(mma_gemm_kernel<2,2>, cudaFuncAttributeMaxDynamicSharedMemorySize, SMEM_REQ);
    cudaFuncSetAttribute(mma_gemm_kernel<3,1>, cudaFuncAttributeMaxDynamicSharedMemorySize, SMEM_REQ);

    __nv_bfloat16 *pxh2, *pwt2, *pwvt, *pqk, *pvt, *pab;
    float *pb2, *psc;
    unsigned *ppool;
    cudaGetSymbolAddress((void**)&pxh2,  g_xh2);
    cudaGetSymbolAddress((void**)&pwt2,  g_wt2);
    cudaGetSymbolAddress((void**)&pwvt,  g_wvt);
    cudaGetSymbolAddress((void**)&pb2,   g_b2);
    cudaGetSymbolAddress((void**)&pqk,   g_qk);
    cudaGetSymbolAddress((void**)&pvt,   g_vt);
    cudaGetSymbolAddress((void**)&pab,   g_ab);
    cudaGetSymbolAddress((void**)&psc,   g_sc);
    cudaGetSymbolAddress((void**)&ppool, g_poolu);

    __nv_bfloat16* pq = pqk;
    __nv_bfloat16* pk = pqk + (long)MTOT*DD;

    // 1. x = leaky(LN(traj@w_mlp)) + le -> bf16 (slot 0)
    build_x_kernel<<<MTOT, 256>>>(traj, labels, w_mlp, b_mlp, ln_g, ln_b, emb);
    // 2. h -> bf16 (slot 1) + pool init
    conv_bf16_kernel<<<(MTOT*DD/4 + 255)/256, 256>>>(h, MTOT*DD/4);
    // 3. transposed weights + packed biases
    convT_all_kernel<<<3*DD, DD>>>(wq, wk, wv, bq, bk);

    // 4. q,k = [x;h] @ [wq;wk] + [bq;bk]  (z=2 batched; skip k-rows >= vl)
    mma_gemm_kernel<1,3><<<dim3(2, 256, 2), 256, SMEM_REQ>>>(
        pxh2, pwt2, pb2, nullptr, pqk, nullptr, valid_len,
        DD, DD, (long)MTOT*DD, (long)DD*DD, (long)MTOT*DD, DD, 1.f);
    // 5. vT[b][d][n] = wvT @ h^T + bv[d]  (skip n-tiles >= vl)
    mma_gemm_kernel<2,2><<<dim3(4, 2, BB), 256, SMEM_REQ>>>(
        pwvt, pxh2 + (long)MTOT*DD, bv, nullptr, pvt, nullptr, valid_len,
        NKV, DD, 0, (long)NKV*DD, (long)DD*NKV, 0, 1.f);
    // 6. scores = q@k^T / 16  (skip n-tiles >= vl)
    mma_gemm_kernel<0,2><<<dim3(4, 4, BB), 256, SMEM_REQ>>>(
        pq, pk, nullptr, psc, nullptr, nullptr, valid_len,
        NKV, DD, (long)TT*DD, (long)NKV*DD, (long)TT*NKV, 0, 0.0625f);
    // 7. masked softmax -> attn bf16
    softmax_kernel<<<BB*TT, 256>>>(valid_len);
    // 8. enc = attn@v, fused max-pool via atomicMax (K-loop limited to ceil(vl/64))
    mma_gemm_kernel<3,1><<<dim3(2, 4, BB), 256, SMEM_REQ>>>(
        pab, pvt, nullptr, nullptr, nullptr, ppool, valid_len,
        DD, NKV, (long)TT*NKV, (long)DD*NKV, 0, 0, 1.f);
    // 9. output = sigmoid((pooled + le) @ w_out + b_out)
    pool_out_kernel<<<BB, 256>>>(labels, emb, w_out, b_out, out);
}

// round 10
// speedup vs baseline: 6.2512x; 1.1633x over previous
#include <cuda_runtime.h>
#include <cuda_bf16.h>
#include <cstdint>
#include <math.h>

#define BB 64
#define TT 512
#define NKV 512
#define DD 256
#define MTOT (BB*TT)
#define EPSLN 1e-5f

// ======================= scratch (device globals) ===========================
__device__ __align__(256) __nv_bfloat16 g_xh2[2*MTOT*DD];   // [0]=x, [1]=h
__device__ __align__(256) __nv_bfloat16 g_wt2[2*DD*DD];     // [0]=wqT, [1]=wkT
__device__ __align__(256) __nv_bfloat16 g_wvt[DD*DD];
__device__ __align__(256) float         g_b2[2*DD];         // bq, bk
__device__ __align__(256) __nv_bfloat16 g_qk[2*MTOT*DD];    // [0]=q, [1]=k
__device__ __align__(256) __nv_bfloat16 g_vt[BB*DD*NKV];
__device__ __align__(256) __nv_bfloat16 g_ab[BB*TT*NKV];
__device__ __align__(256) float         g_sc[BB*TT*NKV];
__device__ __align__(256) unsigned      g_poolu[BB*DD];

// ======================= PTX helpers (baseline ISA only) ====================
__device__ __forceinline__ uint32_t smem_to_u32(const void* p) {
    uint32_t a;
    asm("{ .reg .u64 t; cvta.to.shared.u64 t, %1; cvt.u32.u64 %0, t; }" : "=r"(a) : "l"(p));
    return a;
}
#define CP_ASYNC16(dst_u32, src_ptr) \
    asm volatile("cp.async.cg.shared.global [%0], [%1], 16;" \
        :: "r"(dst_u32), "l"(src_ptr))
#define CP_ASYNC_COMMIT() asm volatile("cp.async.commit_group;" ::: "memory")
#define CP_ASYNC_WAIT0()  asm volatile("cp.async.wait_group 0;" ::: "memory")
#define CP_ASYNC_WAIT1()  asm volatile("cp.async.wait_group 1;" ::: "memory")
#define CP_ASYNC_WAIT2()  asm volatile("cp.async.wait_group 2;" ::: "memory")
#define CP_ASYNC_WAIT3()  asm volatile("cp.async.wait_group 3;" ::: "memory")

__device__ __forceinline__ void ldsm4(uint32_t* r, uint32_t addr) {
    asm volatile("ldmatrix.sync.aligned.m8n8.x4.shared.b16 {%0,%1,%2,%3}, [%4];"
        : "=r"(r[0]), "=r"(r[1]), "=r"(r[2]), "=r"(r[3]) : "r"(addr));
}
__device__ __forceinline__ void mma_bf16(float* c, const uint32_t* a, const uint32_t* b) {
    asm volatile(
        "mma.sync.aligned.m16n8k16.row.col.f32.bf16.bf16.f32 "
        "{%0,%1,%2,%3}, {%4,%5,%6,%7}, {%8,%9}, {%0,%1,%2,%3};"
        : "+f"(c[0]), "+f"(c[1]), "+f"(c[2]), "+f"(c[3])
        : "r"(a[0]), "r"(a[1]), "r"(a[2]), "r"(a[3]), "r"(b[0]), "r"(b[1]));
}

// order-preserving float<->unsigned for atomicMax
__device__ __forceinline__ unsigned encf(float f) {
    unsigned u = __float_as_uint(f);
    return (u & 0x80000000u) ? ~u : (u | 0x80000000u);
}
__device__ __forceinline__ float decf(unsigned u) {
    unsigned b = (u & 0x80000000u) ? (u ^ 0x80000000u) : ~u;
    return __uint_as_float(b);
}

// ======================= reductions =========================================
__device__ __forceinline__ float warp_sum(float v) {
    #pragma unroll
    for (int o = 16; o > 0; o >>= 1) v += __shfl_xor_sync(0xffffffffu, v, o);
    return v;
}
__device__ __forceinline__ float warp_max(float v) {
    #pragma unroll
    for (int o = 16; o > 0; o >>= 1) v = fmaxf(v, __shfl_xor_sync(0xffffffffu, v, o));
    return v;
}
__device__ __forceinline__ float block_sum(float v, float* red) {
    int lane = threadIdx.x & 31, wid = threadIdx.x >> 5;
    v = warp_sum(v);
    if (lane == 0) red[wid] = v;
    __syncthreads();
    v = (threadIdx.x < (blockDim.x >> 5)) ? red[threadIdx.x] : 0.f;
    if (wid == 0) v = warp_sum(v);
    if (threadIdx.x == 0) red[0] = v;
    __syncthreads();
    v = red[0];
    __syncthreads();
    return v;
}

// ======================= elementwise kernels ================================
// warp-per-row: 8 rows per 256-thread block, 8 d-values per lane (contiguous)
__global__ __launch_bounds__(256) void build_x_kernel(
    const float* __restrict__ traj, const int* __restrict__ labels,
    const float* __restrict__ w_mlp, const float* __restrict__ b_mlp,
    const float* __restrict__ ln_g, const float* __restrict__ ln_b,
    const float* __restrict__ emb)
{
    int wid  = threadIdx.x >> 5, lane = threadIdx.x & 31;
    int row  = blockIdx.x*8 + wid;
    int b    = row >> 9;
    int d0   = lane*8;
    float t0 = traj[row*2 + 0];
    float t1 = traj[row*2 + 1];

    float v[8];
    float lsum = 0.f;
    #pragma unroll
    for (int j = 0; j < 8; j += 4) {
        float4 wa = *(const float4*)&w_mlp[d0 + j];
        float4 wb = *(const float4*)&w_mlp[DD + d0 + j];
        float4 bm = *(const float4*)&b_mlp[d0 + j];
        v[j+0] = t0*wa.x + t1*wb.x + bm.x;
        v[j+1] = t0*wa.y + t1*wb.y + bm.y;
        v[j+2] = t0*wa.z + t1*wb.z + bm.z;
        v[j+3] = t0*wa.w + t1*wb.w + bm.w;
        lsum += v[j+0] + v[j+1] + v[j+2] + v[j+3];
    }
    float mean = warp_sum(lsum) * (1.f/DD);
    float lvar = 0.f;
    #pragma unroll
    for (int j = 0; j < 8; j++) { float dv = v[j] - mean; lvar += dv*dv; }
    float rstd = rsqrtf(warp_sum(lvar) * (1.f/DD) + EPSLN);

    int lab = labels[b];
    uint32_t ww[4];
    #pragma unroll
    for (int j = 0; j < 8; j += 2) {
        float g0 = ln_g[d0+j],   g1 = ln_g[d0+j+1];
        float o0 = ln_b[d0+j],   o1 = ln_b[d0+j+1];
        float e0 = emb[lab*DD + d0 + j], e1 = emb[lab*DD + d0 + j + 1];
        float y0 = (v[j]   - mean) * rstd * g0 + o0;
        float y1 = (v[j+1] - mean) * rstd * g1 + o1;
        y0 = (y0 > 0.f) ? y0 : 0.01f*y0;
        y1 = (y1 > 0.f) ? y1 : 0.01f*y1;
        y0 += e0; y1 += e1;
        ww[j>>1] = (uint32_t)__bfloat16_as_ushort(__float2bfloat16(y0))
                 | ((uint32_t)__bfloat16_as_ushort(__float2bfloat16(y1)) << 16);
    }
    *(uint4*)&g_xh2[(long)row*DD + d0] = *(uint4*)ww;
}

// h -> bf16 into g_xh2 slot 1; also zero-init pool buffer
__global__ __launch_bounds__(256) void conv_bf16_kernel(
    const float* __restrict__ in, int n4)
{
    int i = blockIdx.x*256 + threadIdx.x;
    if (i < BB*DD) g_poolu[i] = 0u;
    if (i >= n4) return;
    float4 v = ((const float4*)in)[i];
    uint32_t w0 = (uint32_t)__bfloat16_as_ushort(__float2bfloat16(v.x))
                | ((uint32_t)__bfloat16_as_ushort(__float2bfloat16(v.y)) << 16);
    uint32_t w1 = (uint32_t)__bfloat16_as_ushort(__float2bfloat16(v.z))
                | ((uint32_t)__bfloat16_as_ushort(__float2bfloat16(v.w)) << 16);
    ((uint2*)(g_xh2 + (long)MTOT*DD))[i] = make_uint2(w0, w1);
}

// wq,wk,wv [k][n] -> transposed bf16; pack bq,bk
__global__ __launch_bounds__(256) void convT_all_kernel(
    const float* __restrict__ wq, const float* __restrict__ wk,
    const float* __restrict__ wv,
    const float* __restrict__ bq, const float* __restrict__ bk)
{
    int w = blockIdx.x >> 8;     // 0..2
    int n = blockIdx.x & 255;
    int k = threadIdx.x;
    const float* src = (w == 0) ? wq : (w == 1) ? wk : wv;
    __nv_bfloat16* dst = (w == 0) ? g_wt2 : (w == 1) ? (g_wt2 + DD*DD) : g_wvt;
    dst[n*DD + k] = __float2bfloat16(src[k*DD + n]);
    if (blockIdx.x == 0) g_b2[k] = bq[k];
    if (blockIdx.x == 1) g_b2[DD + k] = bk[k];
}

// warp-per-row softmax: 8 rows per block, 16 contiguous keys per lane
__global__ __launch_bounds__(256) void softmax_kernel(const int* __restrict__ valid_len)
{
    int wid  = threadIdx.x >> 5, lane = threadIdx.x & 31;
    int row  = blockIdx.x*8 + wid;
    int b    = row >> 9;
    int vl   = valid_len[b];
    const float* s = g_sc + (long)row * NKV;
    int j0 = lane*16;

    float v[16];
    float lmax = -3.4e38f;
    #pragma unroll
    for (int j = 0; j < 16; j += 4) {
        float4 f = *(const float4*)&s[j0 + j];
        v[j+0] = (j0+j+0 < vl) ? f.x : -1e9f;
        v[j+1] = (j0+j+1 < vl) ? f.y : -1e9f;
        v[j+2] = (j0+j+2 < vl) ? f.z : -1e9f;
        v[j+3] = (j0+j+3 < vl) ? f.w : -1e9f;
        lmax = fmaxf(lmax, fmaxf(fmaxf(v[j], v[j+1]), fmaxf(v[j+2], v[j+3])));
    }
    float m = warp_max(lmax);
    float lsum = 0.f;
    #pragma unroll
    for (int j = 0; j < 16; j++) { v[j] = __expf(v[j] - m); lsum += v[j]; }
    float inv = 1.f / warp_sum(lsum);

    uint32_t ww[8];
    #pragma unroll
    for (int j = 0; j < 16; j += 2) {
        ww[j>>1] = (uint32_t)__bfloat16_as_ushort(__float2bfloat16(v[j]   * inv))
                 | ((uint32_t)__bfloat16_as_ushort(__float2bfloat16(v[j+1] * inv)) << 16);
    }
    uint4* dst = (uint4*)&g_ab[(long)row*NKV + j0];
    dst[0] = ((uint4*)ww)[0];
    dst[1] = ((uint4*)ww)[1];
}

__global__ __launch_bounds__(256) void pool_out_kernel(
    const int* __restrict__ labels, const float* __restrict__ emb,
    const float* __restrict__ w_out, const float* __restrict__ b_out,
    float* __restrict__ out)
{
    int b = blockIdx.x;
    int d = threadIdx.x;
    float m = decf(g_poolu[b*DD + d]);
    float p = m + emb[labels[b]*DD + d];

    __shared__ float red[32];
    float sum = block_sum(p * w_out[d], red);
    if (threadIdx.x == 0)
        out[b] = 1.f / (1.f + __expf(-(sum + b_out[0])));
}

// ======================= mma.sync GEMM ======================================
// C = scale * A @ B^T (+ bias).  A: [M,K] K-major bf16; B: [Nglob,K] K-major bf16.
// MODE 0: Cf fp32 *scale.  MODE 1: Cb bf16 + bias[z*sBias + n].
// MODE 2: Cb bf16 + bias[m].  MODE 3: no store; atomicMax pooled column max.
// VLM 0: none. 1: K-limit at ceil(vl[z]/32). 2: exit if n0 >= vl[z].
// VLM 3: exit if z==1 && (m0&511) >= vl[m0>>9]  (merged q/k projection).
// Block tile 128x128, K-chunk 32, 4-stage cp.async pipeline, 8 warps (4m x 2n),
// warp tile 32x64. 2 CTAs/SM (regs<=128, smem 80KB/CTA).
#define LDSROW   80                  // 32 bf16 (64B) + 16B pad
#define A_SB     (128*LDSROW)        // 10240 B
#define B_SB     (128*LDSROW)        // 10240 B
#define STAGE    (A_SB + B_SB)       // 20480 B
#define NSTAGE   4
#define SMEM_REQ (NSTAGE*STAGE)      // 81920 B

template<int MODE, int VLM>
__global__ __launch_bounds__(256, 2) void mma_gemm_kernel(
    const __nv_bfloat16* __restrict__ A, const __nv_bfloat16* __restrict__ B,
    const float* __restrict__ bias,
    float* __restrict__ Cf, __nv_bfloat16* __restrict__ Cb,
    unsigned* __restrict__ Pool, const int* __restrict__ vlen,
    int N, int K, long sA, long sB, long sC, long sBias, float scale)
{
    extern __shared__ char dsm[];
    const uint32_t sm0 = smem_to_u32(dsm);

    const int tid  = threadIdx.x;
    const int lane = tid & 31;
    const int w    = tid >> 5;
    const int wm   = w & 3;          // m offset wm*32
    const int wn   = w >> 2;         // n offset wn*64

    const int m0 = blockIdx.y * 128;
    const int n0 = blockIdx.x * 128;

    int nch = K >> 5;
    if (VLM == 1) { int vl = vlen[blockIdx.z]; nch = (vl + 31) >> 5; }
    if (VLM == 2) { if (n0 >= vlen[blockIdx.z]) return; }
    if (VLM == 3) { if (blockIdx.z == 1 && (m0 & 511) >= vlen[m0 >> 9]) return; }

    A += (long)blockIdx.z * sA;
    B += (long)blockIdx.z * sB;
    const long czoff = (long)blockIdx.z * sC;

    float acc[2][8][4] = {};   // [mt][nt][c]

    // K-chunk 32 bf16 = 64B = 4 x 16B segs/row. A:128x4=512, B:512 -> 4 iters.
    auto prefetch = [&](int c) {
        const int kc = c << 5;
        const uint32_t sb = sm0 + (c & (NSTAGE-1)) * STAGE;
        #pragma unroll
        for (int t = 0; t < 4; t++) {
            int idx = t*256 + tid;               // 0..1023
            int row = (idx >> 2) & 127, seg = idx & 3;
            if (idx < 512) {
                CP_ASYNC16(sb + row*LDSROW + seg*16,
                           A + (long)(m0 + row)*K + kc + seg*8);
            } else {
                CP_ASYNC16(sb + A_SB + row*LDSROW + seg*16,
                           B + (long)(n0 + row)*K + kc + seg*8);
            }
        }
        CP_ASYNC_COMMIT();
    };

    for (int p = 0; p < 3 && p < nch; p++) prefetch(p);

    for (int c = 0; c < nch; c++) {
        if (c + 3 < nch)      { prefetch(c + 3); CP_ASYNC_WAIT3(); }
        else if (c + 2 < nch) { CP_ASYNC_WAIT2(); }
        else if (c + 1 < nch) { CP_ASYNC_WAIT1(); }
        else                  { CP_ASYNC_WAIT0(); }
        __syncthreads();

        const uint32_t sb = sm0 + (c & (NSTAGE-1)) * STAGE;
        #pragma unroll
        for (int ks = 0; ks < 2; ks++) {
            uint32_t aF[2][4], bF[8][2];
            {
                const int arow = wm*32 + (lane & 15);
                const int acol = (ks*16 + ((lane >> 4) & 1)*8) * 2;
                #pragma unroll
                for (int mt = 0; mt < 2; mt++)
                    ldsm4(aF[mt], sb + (arow + mt*16)*LDSROW + acol);
            }
            {
                const int bcol = (ks*16 + ((lane >> 3) & 1)*8) * 2;
                #pragma unroll
                for (int g = 0; g < 4; g++) {
                    const int brow = wn*64 + g*16 + ((lane >> 4) & 1)*8 + (lane & 7);
                    uint32_t t4[4];
                    ldsm4(t4, sb + A_SB + brow*LDSROW + bcol);
                    bF[2*g+0][0] = t4[0]; bF[2*g+0][1] = t4[1];
                    bF[2*g+1][0] = t4[2]; bF[2*g+1][1] = t4[3];
                }
            }
            #pragma unroll
            for (int mt = 0; mt < 2; mt++)
                #pragma unroll
                for (int nt = 0; nt < 8; nt++)
                    mma_bf16(acc[mt][nt], aF[mt], bF[nt]);
        }
        __syncthreads();
    }

    // ======================= epilogue =======================================
    if (MODE == 3) {
        #pragma unroll
        for (int nt = 0; nt < 8; nt++) {
            int ng = n0 + wn*64 + nt*8 + (lane & 3)*2;
            float c0 = -3.4e38f, c1 = -3.4e38f;
            #pragma unroll
            for (int mt = 0; mt < 2; mt++) {
                c0 = fmaxf(c0, fmaxf(acc[mt][nt][0], acc[mt][nt][2]));
                c1 = fmaxf(c1, fmaxf(acc[mt][nt][1], acc[mt][nt][3]));
            }
            #pragma unroll
            for (int o = 4; o < 32; o <<= 1) {
                c0 = fmaxf(c0, __shfl_xor_sync(0xffffffffu, c0, o));
                c1 = fmaxf(c1, __shfl_xor_sync(0xffffffffu, c1, o));
            }
            if ((lane >> 2) == 0) {
                atomicMax(&Pool[blockIdx.z*DD + ng],     encf(c0));
                atomicMax(&Pool[blockIdx.z*DD + ng + 1], encf(c1));
            }
        }
        return;
    }
    #pragma unroll
    for (int mt = 0; mt < 2; mt++) {
        #pragma unroll
        for (int nt = 0; nt < 8; nt++) {
            int mg = m0 + wm*32 + mt*16 + (lane >> 2);
            int ng = n0 + wn*64 + nt*8 + (lane & 3)*2;
            float v0 = acc[mt][nt][0], v1 = acc[mt][nt][1];
            float v2 = acc[mt][nt][2], v3 = acc[mt][nt][3];
            if (MODE == 0) {
                *(float2*)&Cf[czoff + (long)mg*N + ng]     = make_float2(v0*scale, v1*scale);
                *(float2*)&Cf[czoff + (long)(mg+8)*N + ng] = make_float2(v2*scale, v3*scale);
            } else {
                if (MODE == 1) {
                    float b0 = bias[blockIdx.z*sBias + ng], b1 = bias[blockIdx.z*sBias + ng + 1];
                    v0 += b0; v1 += b1; v2 += b0; v3 += b1;
                } else {
                    float b0 = bias[mg], b1 = bias[mg+8];
                    v0 += b0; v1 += b0; v2 += b1; v3 += b1;
                }
                uint32_t w0 = (uint32_t)__bfloat16_as_ushort(__float2bfloat16(v0))
                            | ((uint32_t)__bfloat16_as_ushort(__float2bfloat16(v1)) << 16);
                uint32_t w1 = (uint32_t)__bfloat16_as_ushort(__float2bfloat16(v2))
                            | ((uint32_t)__bfloat16_as_ushort(__float2bfloat16(v3)) << 16);
                *(uint32_t*)&Cb[czoff + (long)mg*N + ng]     = w0;
                *(uint32_t*)&Cb[czoff + (long)(mg+8)*N + ng] = w1;
            }
        }
    }
}

// ======================= launch =============================================
extern "C" void kernel_launch(void* const* d_in, const int* in_sizes, int n_in,
                              void* d_out, int out_size)
{
    const float* traj      = (const float*)d_in[0];
    const int*   labels    = (const int*)  d_in[1];
    const float* h         = (const float*)d_in[2];
    const int*   valid_len = (const int*)  d_in[3];
    const float* emb       = (const float*)d_in[4];
    const float* w_mlp     = (const float*)d_in[5];
    const float* b_mlp     = (const float*)d_in[6];
    const float* ln_g      = (const float*)d_in[7];
    const float* ln_b      = (const float*)d_in[8];
    const float* wq        = (const float*)d_in[9];
    const float* wk        = (const float*)d_in[11];
    const float* wv        = (const float*)d_in[13];
    const float* bq        = (const float*)d_in[10];
    const float* bk        = (const float*)d_in[12];
    const float* bv        = (const float*)d_in[14];
    const float* w_out     = (const float*)d_in[15];
    const float* b_out     = (const float*)d_in[16];
    float* out = (float*)d_out;

    cudaFuncSetAttribute(mma_gemm_kernel<0,2>, cudaFuncAttributeMaxDynamicSharedMemorySize, SMEM_REQ);
    cudaFuncSetAttribute(mma_gemm_kernel<1,3>, cudaFuncAttributeMaxDynamicSharedMemorySize, SMEM_REQ);
    cudaFuncSetAttribute(mma_gemm_kernel<2,2>, cudaFuncAttributeMaxDynamicSharedMemorySize, SMEM_REQ);
    cudaFuncSetAttribute(mma_gemm_kernel<3,1>, cudaFuncAttributeMaxDynamicSharedMemorySize, SMEM_REQ);

    __nv_bfloat16 *pxh2, *pwt2, *pwvt, *pqk, *pvt, *pab;
    float *pb2, *psc;
    unsigned *ppool;
    cudaGetSymbolAddress((void**)&pxh2,  g_xh2);
    cudaGetSymbolAddress((void**)&pwt2,  g_wt2);
    cudaGetSymbolAddress((void**)&pwvt,  g_wvt);
    cudaGetSymbolAddress((void**)&pb2,   g_b2);
    cudaGetSymbolAddress((void**)&pqk,   g_qk);
    cudaGetSymbolAddress((void**)&pvt,   g_vt);
    cudaGetSymbolAddress((void**)&pab,   g_ab);
    cudaGetSymbolAddress((void**)&psc,   g_sc);
    cudaGetSymbolAddress((void**)&ppool, g_poolu);

    __nv_bfloat16* pq = pqk;
    __nv_bfloat16* pk = pqk + (long)MTOT*DD;

    // 1. x = leaky(LN(traj@w_mlp)) + le -> bf16 (slot 0); warp-per-row
    build_x_kernel<<<MTOT/8, 256>>>(traj, labels, w_mlp, b_mlp, ln_g, ln_b, emb);
    // 2. h -> bf16 (slot 1) + pool init
    conv_bf16_kernel<<<(MTOT*DD/4 + 255)/256, 256>>>(h, MTOT*DD/4);
    // 3. transposed weights + packed biases
    convT_all_kernel<<<3*DD, DD>>>(wq, wk, wv, bq, bk);

    // 4. q,k = [x;h] @ [wq;wk] + [bq;bk]  (z=2 batched; skip k-rows >= vl)
    mma_gemm_kernel<1,3><<<dim3(2, 256, 2), 256, SMEM_REQ>>>(
        pxh2, pwt2, pb2, nullptr, pqk, nullptr, valid_len,
        DD, DD, (long)MTOT*DD, (long)DD*DD, (long)MTOT*DD, DD, 1.f);
    // 5. vT[b][d][n] = wvT @ h^T + bv[d]  (skip n-tiles >= vl)
    mma_gemm_kernel<2,2><<<dim3(4, 2, BB), 256, SMEM_REQ>>>(
        pwvt, pxh2 + (long)MTOT*DD, bv, nullptr, pvt, nullptr, valid_len,
        NKV, DD, 0, (long)NKV*DD, (long)DD*NKV, 0, 1.f);
    // 6. scores = q@k^T / 16  (skip n-tiles >= vl)
    mma_gemm_kernel<0,2><<<dim3(4, 4, BB), 256, SMEM_REQ>>>(
        pq, pk, nullptr, psc, nullptr, nullptr, valid_len,
        NKV, DD, (long)TT*DD, (long)NKV*DD, (long)TT*NKV, 0, 0.0625f);
    // 7. masked softmax -> attn bf16; warp-per-row
    softmax_kernel<<<MTOT/8, 256>>>(valid_len);
    // 8. enc = attn@v, fused max-pool via atomicMax (K limited to ceil(vl/32))
    mma_gemm_kernel<3,1><<<dim3(2, 4, BB), 256, SMEM_REQ>>>(
        pab, pvt, nullptr, nullptr, nullptr, ppool, valid_len,
        DD, NKV, (long)TT*NKV, (long)DD*NKV, 0, 0, 1.f);
    // 9. output = sigmoid((pooled + le) @ w_out + b_out)
    pool_out_kernel<<<BB, 256>>>(labels, emb, w_out, b_out, out);
}

// round 11
// speedup vs baseline: 6.3598x; 1.0174x over previous
#include <cuda_runtime.h>
#include <cuda_bf16.h>
#include <cstdint>
#include <math.h>

#define BB 64
#define TT 512
#define NKV 512
#define DD 256
#define MTOT (BB*TT)
#define EPSLN 1e-5f

// ======================= scratch (device globals) ===========================
__device__ __align__(256) __nv_bfloat16 g_xh2[2*MTOT*DD];   // [0]=x, [1]=h
__device__ __align__(256) __nv_bfloat16 g_wt2[2*DD*DD];     // [0]=wqT(/16), [1]=wkT
__device__ __align__(256) __nv_bfloat16 g_wvt[DD*DD];
__device__ __align__(256) float         g_b2[2*DD];         // bq/16, bk
__device__ __align__(256) __nv_bfloat16 g_qk[2*MTOT*DD];    // [0]=q/16, [1]=k
__device__ __align__(256) __nv_bfloat16 g_vt[BB*DD*NKV];
__device__ __align__(256) unsigned      g_poolu[BB*DD];

// ======================= PTX helpers (baseline ISA only) ====================
__device__ __forceinline__ uint32_t smem_to_u32(const void* p) {
    uint32_t a;
    asm("{ .reg .u64 t; cvta.to.shared.u64 t, %1; cvt.u32.u64 %0, t; }" : "=r"(a) : "l"(p));
    return a;
}
#define CP_ASYNC16(dst_u32, src_ptr) \
    asm volatile("cp.async.cg.shared.global [%0], [%1], 16;" \
        :: "r"(dst_u32), "l"(src_ptr))
#define CP_ASYNC_COMMIT() asm volatile("cp.async.commit_group;" ::: "memory")
#define CP_ASYNC_WAIT0()  asm volatile("cp.async.wait_group 0;" ::: "memory")
#define CP_ASYNC_WAIT1()  asm volatile("cp.async.wait_group 1;" ::: "memory")
#define CP_ASYNC_WAIT2()  asm volatile("cp.async.wait_group 2;" ::: "memory")
#define CP_ASYNC_WAIT3()  asm volatile("cp.async.wait_group 3;" ::: "memory")

__device__ __forceinline__ void ldsm4(uint32_t* r, uint32_t addr) {
    asm volatile("ldmatrix.sync.aligned.m8n8.x4.shared.b16 {%0,%1,%2,%3}, [%4];"
        : "=r"(r[0]), "=r"(r[1]), "=r"(r[2]), "=r"(r[3]) : "r"(addr));
}
__device__ __forceinline__ void mma_bf16(float* c, const uint32_t* a, const uint32_t* b) {
    asm volatile(
        "mma.sync.aligned.m16n8k16.row.col.f32.bf16.bf16.f32 "
        "{%0,%1,%2,%3}, {%4,%5,%6,%7}, {%8,%9}, {%0,%1,%2,%3};"
        : "+f"(c[0]), "+f"(c[1]), "+f"(c[2]), "+f"(c[3])
        : "r"(a[0]), "r"(a[1]), "r"(a[2]), "r"(a[3]), "r"(b[0]), "r"(b[1]));
}

// order-preserving float<->unsigned for atomicMax
__device__ __forceinline__ unsigned encf(float f) {
    unsigned u = __float_as_uint(f);
    return (u & 0x80000000u) ? ~u : (u | 0x80000000u);
}
__device__ __forceinline__ float decf(unsigned u) {
    unsigned b = (u & 0x80000000u) ? (u ^ 0x80000000u) : ~u;
    return __uint_as_float(b);
}
__device__ __forceinline__ uint32_t pack_bf16(float a, float b) {
    return (uint32_t)__bfloat16_as_ushort(__float2bfloat16(a))
         | ((uint32_t)__bfloat16_as_ushort(__float2bfloat16(b)) << 16);
}

// ======================= reductions =========================================
__device__ __forceinline__ float warp_sum(float v) {
    #pragma unroll
    for (int o = 16; o > 0; o >>= 1) v += __shfl_xor_sync(0xffffffffu, v, o);
    return v;
}
__device__ __forceinline__ float warp_max(float v) {
    #pragma unroll
    for (int o = 16; o > 0; o >>= 1) v = fmaxf(v, __shfl_xor_sync(0xffffffffu, v, o));
    return v;
}
__device__ __forceinline__ float block_sum(float v, float* red) {
    int lane = threadIdx.x & 31, wid = threadIdx.x >> 5;
    v = warp_sum(v);
    if (lane == 0) red[wid] = v;
    __syncthreads();
    v = (threadIdx.x < (blockDim.x >> 5)) ? red[threadIdx.x] : 0.f;
    if (wid == 0) v = warp_sum(v);
    if (threadIdx.x == 0) red[0] = v;
    __syncthreads();
    v = red[0];
    __syncthreads();
    return v;
}

// ======================= elementwise kernels ================================
// warp-per-row: 8 rows per 256-thread block, 8 d-values per lane
__global__ __launch_bounds__(256) void build_x_kernel(
    const float* __restrict__ traj, const int* __restrict__ labels,
    const float* __restrict__ w_mlp, const float* __restrict__ b_mlp,
    const float* __restrict__ ln_g, const float* __restrict__ ln_b,
    const float* __restrict__ emb)
{
    int wid  = threadIdx.x >> 5, lane = threadIdx.x & 31;
    int row  = blockIdx.x*8 + wid;
    int b    = row >> 9;
    int d0   = lane*8;
    float t0 = traj[row*2 + 0];
    float t1 = traj[row*2 + 1];

    float v[8];
    float lsum = 0.f;
    #pragma unroll
    for (int j = 0; j < 8; j += 4) {
        float4 wa = *(const float4*)&w_mlp[d0 + j];
        float4 wb = *(const float4*)&w_mlp[DD + d0 + j];
        float4 bm = *(const float4*)&b_mlp[d0 + j];
        v[j+0] = t0*wa.x + t1*wb.x + bm.x;
        v[j+1] = t0*wa.y + t1*wb.y + bm.y;
        v[j+2] = t0*wa.z + t1*wb.z + bm.z;
        v[j+3] = t0*wa.w + t1*wb.w + bm.w;
        lsum += v[j+0] + v[j+1] + v[j+2] + v[j+3];
    }
    float mean = warp_sum(lsum) * (1.f/DD);
    float lvar = 0.f;
    #pragma unroll
    for (int j = 0; j < 8; j++) { float dv = v[j] - mean; lvar += dv*dv; }
    float rstd = rsqrtf(warp_sum(lvar) * (1.f/DD) + EPSLN);

    int lab = labels[b];
    uint32_t ww[4];
    #pragma unroll
    for (int j = 0; j < 8; j += 2) {
        float y0 = (v[j]   - mean) * rstd * ln_g[d0+j]   + ln_b[d0+j];
        float y1 = (v[j+1] - mean) * rstd * ln_g[d0+j+1] + ln_b[d0+j+1];
        y0 = (y0 > 0.f) ? y0 : 0.01f*y0;
        y1 = (y1 > 0.f) ? y1 : 0.01f*y1;
        y0 += emb[lab*DD + d0 + j];
        y1 += emb[lab*DD + d0 + j + 1];
        ww[j>>1] = pack_bf16(y0, y1);
    }
    *(uint4*)&g_xh2[(long)row*DD + d0] = *(uint4*)ww;
}

// h -> bf16 into g_xh2 slot 1; also zero-init pool buffer
__global__ __launch_bounds__(256) void conv_bf16_kernel(
    const float* __restrict__ in, int n4)
{
    int i = blockIdx.x*256 + threadIdx.x;
    if (i < BB*DD) g_poolu[i] = 0u;
    if (i >= n4) return;
    float4 v = ((const float4*)in)[i];
    ((uint2*)(g_xh2 + (long)MTOT*DD))[i] =
        make_uint2(pack_bf16(v.x, v.y), pack_bf16(v.z, v.w));
}

// wq,wk,wv [k][n] -> transposed bf16; wq and bq pre-scaled by 1/16 (1/sqrt(D))
__global__ __launch_bounds__(256) void convT_all_kernel(
    const float* __restrict__ wq, const float* __restrict__ wk,
    const float* __restrict__ wv,
    const float* __restrict__ bq, const float* __restrict__ bk)
{
    int w = blockIdx.x >> 8;     // 0..2
    int n = blockIdx.x & 255;
    int k = threadIdx.x;
    const float* src = (w == 0) ? wq : (w == 1) ? wk : wv;
    __nv_bfloat16* dst = (w == 0) ? g_wt2 : (w == 1) ? (g_wt2 + DD*DD) : g_wvt;
    float sc = (w == 0) ? 0.0625f : 1.f;
    dst[n*DD + k] = __float2bfloat16(src[k*DD + n] * sc);
    if (blockIdx.x == 0) g_b2[k] = bq[k] * 0.0625f;
    if (blockIdx.x == 1) g_b2[DD + k] = bk[k];
}

__global__ __launch_bounds__(256) void pool_out_kernel(
    const int* __restrict__ labels, const float* __restrict__ emb,
    const float* __restrict__ w_out, const float* __restrict__ b_out,
    float* __restrict__ out)
{
    int b = blockIdx.x;
    int d = threadIdx.x;
    float m = decf(g_poolu[b*DD + d]);
    float p = m + emb[labels[b]*DD + d];

    __shared__ float red[32];
    float sum = block_sum(p * w_out[d], red);
    if (threadIdx.x == 0)
        out[b] = 1.f / (1.f + __expf(-(sum + b_out[0])));
}

// ======================= mma.sync GEMM (projections) ========================
// MODE 1: Cb bf16 + bias[z*sBias + n].  MODE 2: Cb bf16 + bias[m].
// VLM 2: exit if n0 >= vl[z]. VLM 3: exit if z==1 && (m0&511) >= vl[m0>>9].
#define LDSROW   80
#define A_SB     (128*LDSROW)
#define B_SB     (128*LDSROW)
#define STAGE    (A_SB + B_SB)
#define NSTAGE   4
#define SMEM_REQ (NSTAGE*STAGE)      // 81920 B

template<int MODE, int VLM>
__global__ __launch_bounds__(256, 2) void mma_gemm_kernel(
    const __nv_bfloat16* __restrict__ A, const __nv_bfloat16* __restrict__ B,
    const float* __restrict__ bias, __nv_bfloat16* __restrict__ Cb,
    const int* __restrict__ vlen,
    int N, int K, long sA, long sB, long sC, long sBias)
{
    extern __shared__ char dsm[];
    const uint32_t sm0 = smem_to_u32(dsm);

    const int tid  = threadIdx.x;
    const int lane = tid & 31;
    const int w    = tid >> 5;
    const int wm   = w & 3;
    const int wn   = w >> 2;

    const int m0 = blockIdx.y * 128;
    const int n0 = blockIdx.x * 128;

    int nch = K >> 5;
    if (VLM == 2) { if (n0 >= vlen[blockIdx.z]) return; }
    if (VLM == 3) { if (blockIdx.z == 1 && (m0 & 511) >= vlen[m0 >> 9]) return; }

    A += (long)blockIdx.z * sA;
    B += (long)blockIdx.z * sB;
    const long czoff = (long)blockIdx.z * sC;

    float acc[2][8][4] = {};

    auto prefetch = [&](int c) {
        const int kc = c << 5;
        const uint32_t sb = sm0 + (c & (NSTAGE-1)) * STAGE;
        #pragma unroll
        for (int t = 0; t < 4; t++) {
            int idx = t*256 + tid;
            int row = (idx >> 2) & 127, seg = idx & 3;
            if (idx < 512) {
                CP_ASYNC16(sb + row*LDSROW + seg*16,
                           A + (long)(m0 + row)*K + kc + seg*8);
            } else {
                CP_ASYNC16(sb + A_SB + row*LDSROW + seg*16,
                           B + (long)(n0 + row)*K + kc + seg*8);
            }
        }
        CP_ASYNC_COMMIT();
    };

    for (int p = 0; p < 3 && p < nch; p++) prefetch(p);

    for (int c = 0; c < nch; c++) {
        if (c + 3 < nch)      { prefetch(c + 3); CP_ASYNC_WAIT3(); }
        else if (c + 2 < nch) { CP_ASYNC_WAIT2(); }
        else if (c + 1 < nch) { CP_ASYNC_WAIT1(); }
        else                  { CP_ASYNC_WAIT0(); }
        __syncthreads();

        const uint32_t sb = sm0 + (c & (NSTAGE-1)) * STAGE;
        #pragma unroll
        for (int ks = 0; ks < 2; ks++) {
            uint32_t aF[2][4], bF[8][2];
            {
                const int arow = wm*32 + (lane & 15);
                const int acol = (ks*16 + ((lane >> 4) & 1)*8) * 2;
                #pragma unroll
                for (int mt = 0; mt < 2; mt++)
                    ldsm4(aF[mt], sb + (arow + mt*16)*LDSROW + acol);
            }
            {
                const int bcol = (ks*16 + ((lane >> 3) & 1)*8) * 2;
                #pragma unroll
                for (int g = 0; g < 4; g++) {
                    const int brow = wn*64 + g*16 + ((lane >> 4) & 1)*8 + (lane & 7);
                    uint32_t t4[4];
                    ldsm4(t4, sb + A_SB + brow*LDSROW + bcol);
                    bF[2*g+0][0] = t4[0]; bF[2*g+0][1] = t4[1];
                    bF[2*g+1][0] = t4[2]; bF[2*g+1][1] = t4[3];
                }
            }
            #pragma unroll
            for (int mt = 0; mt < 2; mt++)
                #pragma unroll
                for (int nt = 0; nt < 8; nt++)
                    mma_bf16(acc[mt][nt], aF[mt], bF[nt]);
        }
        __syncthreads();
    }

    #pragma unroll
    for (int mt = 0; mt < 2; mt++) {
        #pragma unroll
        for (int nt = 0; nt < 8; nt++) {
            int mg = m0 + wm*32 + mt*16 + (lane >> 2);
            int ng = n0 + wn*64 + nt*8 + (lane & 3)*2;
            float v0 = acc[mt][nt][0], v1 = acc[mt][nt][1];
            float v2 = acc[mt][nt][2], v3 = acc[mt][nt][3];
            if (MODE == 1) {
                float b0 = bias[blockIdx.z*sBias + ng], b1 = bias[blockIdx.z*sBias + ng + 1];
                v0 += b0; v1 += b1; v2 += b0; v3 += b1;
            } else {
                float b0 = bias[mg], b1 = bias[mg+8];
                v0 += b0; v1 += b0; v2 += b1; v3 += b1;
            }
            *(uint32_t*)&Cb[czoff + (long)mg*N + ng]     = pack_bf16(v0, v1);
            *(uint32_t*)&Cb[czoff + (long)(mg+8)*N + ng] = pack_bf16(v2, v3);
        }
    }
}

// ======================= flash attention (scores+softmax+PV+pool) ===========
// CTA: 128 q-rows of one batch. 8 warps, warp owns 16 q-rows x all keys.
// kv-tiles of 64 keys, double-buffered. O accumulated in regs; epilogue
// normalizes and atomicMax-pools. q is pre-scaled by 1/sqrt(D).
#define QROW   528                   // 256 bf16 (512B) + 16B pad
#define KROW   528
#define VROW   144                   // 64 bf16 (128B) + 16B pad
#define Q_SB   (128*QROW)            // 67584
#define K_SB   (64*KROW)             // 33792
#define V_SB   (256*VROW)            // 36864
#define KV_SB  (K_SB + V_SB)         // 70656
#define FL_SMEM (Q_SB + 2*KV_SB)     // 208896

__global__ __launch_bounds__(256, 1) void flash_kernel(const int* __restrict__ vlen)
{
    extern __shared__ char dsm[];
    const uint32_t smQ  = smem_to_u32(dsm);
    const uint32_t smKV = smQ + Q_SB;
    const int tid = threadIdx.x, lane = tid & 31, wid = tid >> 5;
    const int b = blockIdx.y, qt = blockIdx.x;
    const int vl = vlen[b];
    const int ntiles = (vl + 63) >> 6;

    const __nv_bfloat16* Qg = g_qk + ((long)(b*TT + qt*128))*DD;
    const __nv_bfloat16* Kg = g_qk + (long)MTOT*DD + (long)b*NKV*DD;
    const __nv_bfloat16* Vg = g_vt + (long)b*DD*NKV;

    // Q tile: 128 rows x 32 16B-segs
    #pragma unroll
    for (int t = 0; t < 16; t++) {
        int idx = t*256 + tid, row = idx >> 5, seg = idx & 31;
        CP_ASYNC16(smQ + row*QROW + seg*16, Qg + (long)row*DD + seg*8);
    }
    CP_ASYNC_COMMIT();

    auto prefetchKV = [&](int kt) {
        uint32_t sb = smKV + (kt & 1) * KV_SB;
        #pragma unroll
        for (int t = 0; t < 16; t++) {
            int idx = t*256 + tid;
            if (idx < 2048) {                 // K: 64 key-rows x 32 segs
                int row = idx >> 5, seg = idx & 31;
                CP_ASYNC16(sb + row*KROW + seg*16,
                           Kg + (long)(kt*64 + row)*DD + seg*8);
            } else {                          // V^T: 256 d-rows x 8 segs
                int j = idx - 2048;
                int row = j >> 3, seg = j & 7;
                CP_ASYNC16(sb + K_SB + row*VROW + seg*16,
                           Vg + (long)row*NKV + kt*64 + seg*8);
            }
        }
        CP_ASYNC_COMMIT();
    };
    prefetchKV(0);

    float o[32][4];
    #pragma unroll
    for (int i = 0; i < 32; i++) o[i][0] = o[i][1] = o[i][2] = o[i][3] = 0.f;
    float m0 = -1e30f, m1 = -1e30f, l0 = 0.f, l1 = 0.f;

    for (int kt = 0; kt < ntiles; kt++) {
        if (kt + 1 < ntiles) {
            __syncthreads();                 // all warps done with buffer (kt+1)&1
            prefetchKV(kt + 1);
            CP_ASYNC_WAIT1();                // Q + KV(kt) complete
        } else {
            CP_ASYNC_WAIT0();
        }
        __syncthreads();
        const uint32_t sb = smKV + (kt & 1) * KV_SB;

        // ---- S = q_tile @ k_tile^T  (warp: 16 q x 64 keys) ----
        float s[8][4] = {};
        #pragma unroll
        for (int ks = 0; ks < 16; ks++) {
            uint32_t aF[4];
            ldsm4(aF, smQ + (wid*16 + (lane & 15))*QROW
                        + (ks*16 + ((lane >> 4) & 1)*8)*2);
            #pragma unroll
            for (int g2 = 0; g2 < 4; g2++) {
                uint32_t t4[4];
                ldsm4(t4, sb + (g2*16 + ((lane >> 4) & 1)*8 + (lane & 7))*KROW
                            + (ks*16 + ((lane >> 3) & 1)*8)*2);
                mma_bf16(s[2*g2+0], aF, t4);
                mma_bf16(s[2*g2+1], aF, t4 + 2);
            }
        }
        // ---- mask last tile ----
        if (kt == ntiles - 1) {
            int kbase = kt*64 + 2*(lane & 3);
            #pragma unroll
            for (int nt = 0; nt < 8; nt++) {
                int k0 = kbase + nt*8;
                if (k0     >= vl) { s[nt][0] = -1e9f; s[nt][2] = -1e9f; }
                if (k0 + 1 >= vl) { s[nt][1] = -1e9f; s[nt][3] = -1e9f; }
            }
        }
        // ---- online softmax (rows g = lane>>2 and g+8) ----
        float rm0 = -1e30f, rm1 = -1e30f;
        #pragma unroll
        for (int nt = 0; nt < 8; nt++) {
            rm0 = fmaxf(rm0, fmaxf(s[nt][0], s[nt][1]));
            rm1 = fmaxf(rm1, fmaxf(s[nt][2], s[nt][3]));
        }
        rm0 = fmaxf(rm0, __shfl_xor_sync(0xffffffffu, rm0, 1));
        rm0 = fmaxf(rm0, __shfl_xor_sync(0xffffffffu, rm0, 2));
        rm1 = fmaxf(rm1, __shfl_xor_sync(0xffffffffu, rm1, 1));
        rm1 = fmaxf(rm1, __shfl_xor_sync(0xffffffffu, rm1, 2));
        float m0n = fmaxf(m0, rm0), m1n = fmaxf(m1, rm1);
        float f0 = __expf(m0 - m0n), f1 = __expf(m1 - m1n);

        uint32_t pr[8][2];
        float ts0 = 0.f, ts1 = 0.f;
        #pragma unroll
        for (int nt = 0; nt < 8; nt++) {
            float p0 = __expf(s[nt][0] - m0n), p1 = __expf(s[nt][1] - m0n);
            float p2 = __expf(s[nt][2] - m1n), p3 = __expf(s[nt][3] - m1n);
            ts0 += p0 + p1; ts1 += p2 + p3;
            pr[nt][0] = pack_bf16(p0, p1);
            pr[nt][1] = pack_bf16(p2, p3);
        }
        ts0 += __shfl_xor_sync(0xffffffffu, ts0, 1);
        ts0 += __shfl_xor_sync(0xffffffffu, ts0, 2);
        ts1 += __shfl_xor_sync(0xffffffffu, ts1, 1);
        ts1 += __shfl_xor_sync(0xffffffffu, ts1, 2);
        l0 = l0*f0 + ts0;  l1 = l1*f1 + ts1;
        m0 = m0n;          m1 = m1n;
        #pragma unroll
        for (int dt = 0; dt < 32; dt++) {
            o[dt][0] *= f0; o[dt][1] *= f0;
            o[dt][2] *= f1; o[dt][3] *= f1;
        }
        // ---- O += P @ V  (A = P in-register, B = V^T tile) ----
        #pragma unroll
        for (int j = 0; j < 4; j++) {
            uint32_t pa[4] = { pr[2*j][0], pr[2*j][1], pr[2*j+1][0], pr[2*j+1][1] };
            #pragma unroll
            for (int dt2 = 0; dt2 < 16; dt2++) {
                uint32_t t4[4];
                ldsm4(t4, sb + K_SB
                          + (dt2*16 + ((lane >> 4) & 1)*8 + (lane & 7))*VROW
                          + (j*16 + ((lane >> 3) & 1)*8)*2);
                mma_bf16(o[2*dt2+0], pa, t4);
                mma_bf16(o[2*dt2+1], pa, t4 + 2);
            }
        }
    }

    // ---- epilogue: normalize, pooled max over q-rows, atomicMax ----
    float inv0 = 1.f / l0, inv1 = 1.f / l1;
    #pragma unroll
    for (int dt = 0; dt < 32; dt++) {
        float c0 = fmaxf(o[dt][0]*inv0, o[dt][2]*inv1);
        float c1 = fmaxf(o[dt][1]*inv0, o[dt][3]*inv1);
        #pragma unroll
        for (int off = 4; off < 32; off <<= 1) {
            c0 = fmaxf(c0, __shfl_xor_sync(0xffffffffu, c0, off));
            c1 = fmaxf(c1, __shfl_xor_sync(0xffffffffu, c1, off));
        }
        if (lane < 4) {
            int d = dt*8 + 2*lane;
            atomicMax(&g_poolu[b*DD + d],     encf(c0));
            atomicMax(&g_poolu[b*DD + d + 1], encf(c1));
        }
    }
}

// ======================= launch =============================================
extern "C" void kernel_launch(void* const* d_in, const int* in_sizes, int n_in,
                              void* d_out, int out_size)
{
    const float* traj      = (const float*)d_in[0];
    const int*   labels    = (const int*)  d_in[1];
    const float* h         = (const float*)d_in[2];
    const int*   valid_len = (const int*)  d_in[3];
    const float* emb       = (const float*)d_in[4];
    const float* w_mlp     = (const float*)d_in[5];
    const float* b_mlp     = (const float*)d_in[6];
    const float* ln_g      = (const float*)d_in[7];
    const float* ln_b      = (const float*)d_in[8];
    const float* wq        = (const float*)d_in[9];
    const float* wk        = (const float*)d_in[11];
    const float* wv        = (const float*)d_in[13];
    const float* bq        = (const float*)d_in[10];
    const float* bk        = (const float*)d_in[12];
    const float* bv        = (const float*)d_in[14];
    const float* w_out     = (const float*)d_in[15];
    const float* b_out     = (const float*)d_in[16];
    float* out = (float*)d_out;

    cudaFuncSetAttribute(mma_gemm_kernel<1,3>, cudaFuncAttributeMaxDynamicSharedMemorySize, SMEM_REQ);
    cudaFuncSetAttribute(mma_gemm_kernel<2,2>, cudaFuncAttributeMaxDynamicSharedMemorySize, SMEM_REQ);
    cudaFuncSetAttribute(flash_kernel, cudaFuncAttributeMaxDynamicSharedMemorySize, FL_SMEM);

    __nv_bfloat16 *pxh2, *pwt2, *pwvt, *pqk, *pvt;
    float *pb2;
    cudaGetSymbolAddress((void**)&pxh2,  g_xh2);
    cudaGetSymbolAddress((void**)&pwt2,  g_wt2);
    cudaGetSymbolAddress((void**)&pwvt,  g_wvt);
    cudaGetSymbolAddress((void**)&pb2,   g_b2);
    cudaGetSymbolAddress((void**)&pqk,   g_qk);
    cudaGetSymbolAddress((void**)&pvt,   g_vt);

    // 1. x = leaky(LN(traj@w_mlp)) + le -> bf16 (slot 0); warp-per-row
    build_x_kernel<<<MTOT/8, 256>>>(traj, labels, w_mlp, b_mlp, ln_g, ln_b, emb);
    // 2. h -> bf16 (slot 1) + pool init
    conv_bf16_kernel<<<(MTOT*DD/4 + 255)/256, 256>>>(h, MTOT*DD/4);
    // 3. transposed weights (+ q pre-scale 1/16) + packed biases
    convT_all_kernel<<<3*DD, DD>>>(wq, wk, wv, bq, bk);

    // 4. q/16, k = [x;h] @ [wq/16; wk] + [bq/16; bk]  (z=2; skip k-rows >= vl)
    mma_gemm_kernel<1,3><<<dim3(2, 256, 2), 256, SMEM_REQ>>>(
        pxh2, pwt2, pb2, pqk, valid_len,
        DD, DD, (long)MTOT*DD, (long)DD*DD, (long)MTOT*DD, DD);
    // 5. vT[b][d][n] = wvT @ h^T + bv[d]  (skip n-tiles >= vl)
    mma_gemm_kernel<2,2><<<dim3(4, 2, BB), 256, SMEM_REQ>>>(
        pwvt, pxh2 + (long)MTOT*DD, bv, pvt, valid_len,
        NKV, DD, 0, (long)NKV*DD, (long)DD*NKV, 0);
    // 6. flash attention: scores + softmax + PV + max-pool (fused)
    flash_kernel<<<dim3(4, BB), 256, FL_SMEM>>>(valid_len);
    // 7. output = sigmoid((pooled + le) @ w_out + b_out)
    pool_out_kernel<<<BB, 256>>>(labels, emb, w_out, b_out, out);
}